// round 1
// baseline (speedup 1.0000x reference)
#include <cuda_runtime.h>
#include <math.h>

#define Dm   768
#define SEQm 512
#define NFS  1024   // B(2) * S(512)
#define LC   103
#define ACLS 119
#define TCLS 11

// ---------------- scratch (static device globals; no allocation) ----------------
__device__ float g_M[Dm*Dm];        // Wq @ Wk^T
__device__ float g_t[NFS*Dm];       // fact_emb @ M + Wk@bq
__device__ float g_wv1[Dm];         // Wv @ w_dprob
__device__ float g_tbias[Dm];       // Wk @ bq
__device__ float g_cbv;             // bv . w_dprob
__device__ float g_v1[LC*SEQm];     // law_embs . wv1 + cbv
__device__ float g_laws2[2*LC*SEQm];
__device__ float g_scores2[2*LC];

__device__ __forceinline__ float warp_sum(float s){
  #pragma unroll
  for (int o=16;o>0;o>>=1) s += __shfl_xor_sync(0xffffffffu, s, o);
  return s;
}

// ---------------- small precompute: wv1, tbias, cbv ----------------
__global__ void prep_kernel(const float* __restrict__ Wk, const float* __restrict__ bq,
                            const float* __restrict__ Wv, const float* __restrict__ wd,
                            const float* __restrict__ bv){
  int warp = (blockIdx.x*blockDim.x + threadIdx.x) >> 5;
  int lane = threadIdx.x & 31;
  if (warp < Dm){
    const float* row = Wv + (size_t)warp*Dm;        // wv1[i] = sum_j Wv[i,j]*wd[j]
    float s=0.f;
    for (int k=lane;k<Dm;k+=32) s += row[k]*wd[k];
    s = warp_sum(s);
    if (!lane) g_wv1[warp]=s;
  } else if (warp < 2*Dm){
    int n = warp - Dm;                               // tbias[n] = sum_k Wk[n,k]*bq[k]
    const float* row = Wk + (size_t)n*Dm;
    float s=0.f;
    for (int k=lane;k<Dm;k+=32) s += row[k]*bq[k];
    s = warp_sum(s);
    if (!lane) g_tbias[n]=s;
  } else if (warp == 2*Dm){
    float s=0.f;
    for (int k=lane;k<Dm;k+=32) s += bv[k]*wd[k];
    s = warp_sum(s);
    if (!lane) g_cbv=s;
  }
}

// ---------------- 128x128x8 fp32 tiled GEMM: C = A @ B (+bias), opt. B transposed ----------------
template<bool TRANSB>
__global__ void __launch_bounds__(256) gemm128(const float* __restrict__ A,
                                               const float* __restrict__ B,
                                               float* __restrict__ C,
                                               int M, int N, int K,
                                               const float* __restrict__ bias){
  __shared__ float As[8][132];
  __shared__ float Bs[8][132];
  int m0 = blockIdx.x*128, n0 = blockIdx.y*128;
  int tid = threadIdx.x;
  int tx = tid & 15, ty = tid >> 4;
  int hm = tid >> 1, hk = (tid & 1)*4;
  float acc[8][8];
  #pragma unroll
  for (int i=0;i<8;i++)
    #pragma unroll
    for (int j=0;j<8;j++) acc[i][j]=0.f;

  for (int k0=0;k0<K;k0+=8){
    float4 av = *(const float4*)(A + (size_t)(m0+hm)*K + k0 + hk);
    float4 bw;
    if (TRANSB) bw = *(const float4*)(B + (size_t)(n0+hm)*K + k0 + hk);
    else        bw = *(const float4*)(B + (size_t)(k0 + (tid>>5))*N + n0 + (tid&31)*4);
    __syncthreads();
    As[hk+0][hm]=av.x; As[hk+1][hm]=av.y; As[hk+2][hm]=av.z; As[hk+3][hm]=av.w;
    if (TRANSB){ Bs[hk+0][hm]=bw.x; Bs[hk+1][hm]=bw.y; Bs[hk+2][hm]=bw.z; Bs[hk+3][hm]=bw.w; }
    else       { *(float4*)&Bs[tid>>5][(tid&31)*4] = bw; }
    __syncthreads();
    #pragma unroll
    for (int k=0;k<8;k++){
      float a[8], b[8];
      *(float4*)&a[0] = *(const float4*)&As[k][ty*8];
      *(float4*)&a[4] = *(const float4*)&As[k][ty*8+4];
      *(float4*)&b[0] = *(const float4*)&Bs[k][tx*8];
      *(float4*)&b[4] = *(const float4*)&Bs[k][tx*8+4];
      #pragma unroll
      for (int i=0;i<8;i++)
        #pragma unroll
        for (int j=0;j<8;j++)
          acc[i][j] += a[i]*b[j];
    }
  }
  #pragma unroll
  for (int i=0;i<8;i++){
    size_t row = (size_t)(m0 + ty*8 + i);
    #pragma unroll
    for (int j=0;j<8;j+=4){
      int col = n0 + tx*8 + j;
      float4 v = make_float4(acc[i][j], acc[i][j+1], acc[i][j+2], acc[i][j+3]);
      if (bias){ v.x+=bias[col]; v.y+=bias[col+1]; v.z+=bias[col+2]; v.w+=bias[col+3]; }
      *(float4*)(C + row*N + col) = v;
    }
  }
}

// ---------------- v1[l,r] = law_embs[l,r,:].wv1 + cbv ----------------
__global__ void v1_kernel(const float* __restrict__ y){
  int row = (blockIdx.x*blockDim.x + threadIdx.x) >> 5;
  if (row >= LC*SEQm) return;
  int lane = threadIdx.x & 31;
  const float4* p = (const float4*)(y + (size_t)row*Dm);
  float s = 0.f;
  #pragma unroll
  for (int k=lane;k<Dm/4;k+=32){
    float4 a = p[k];
    float4 b = *(const float4*)(g_wv1 + 4*k);
    s += a.x*b.x + a.y*b.y + a.z*b.z + a.w*b.w;
  }
  s = warp_sum(s);
  if (!lane) g_v1[row] = s + g_cbv;
}

// ---------------- fused score-GEMM + online softmax + scalar-V accumulation ----------------
// For block (fs_tile, l): S[m,r] = t[m,:].y[l,r,:]/sqrt(D) + mask[l,r]; softmax over r;
// laws2[f,l,s] = sum_r softmax * v1[l,r] + b_dprob
__global__ void __launch_bounds__(256) attn_kernel(const float* __restrict__ y,
                                                   const float* __restrict__ mask,
                                                   const float* __restrict__ bdp){
  __shared__ float As[8][132];
  __shared__ float Bs[8][132];
  __shared__ float v1s[128];
  __shared__ float ms[128];
  int l  = blockIdx.y;
  int m0 = blockIdx.x*128;
  int tid = threadIdx.x;
  int tx = tid & 15, ty = tid >> 4;
  int hm = tid >> 1, hk = (tid & 1)*4;
  const float scl = 0.03608439182435161f;   // 1/sqrt(768)
  const float* yl = y + (size_t)l*SEQm*Dm;

  float row_m[8], row_s[8], row_a[8];
  #pragma unroll
  for (int i=0;i<8;i++){ row_m[i]=-1e30f; row_s[i]=0.f; row_a[i]=0.f; }

  for (int n0=0;n0<SEQm;n0+=128){
    __syncthreads();                          // protect v1s/ms vs previous epilogue readers
    if (tid<128){ v1s[tid]=g_v1[l*SEQm+n0+tid]; ms[tid]=mask[l*SEQm+n0+tid]; }
    float acc[8][8];
    #pragma unroll
    for (int i=0;i<8;i++)
      #pragma unroll
      for (int j=0;j<8;j++) acc[i][j]=0.f;

    for (int k0=0;k0<Dm;k0+=8){
      float4 av = *(const float4*)(g_t + (size_t)(m0+hm)*Dm + k0 + hk);
      float4 bw = *(const float4*)(yl  + (size_t)(n0+hm)*Dm + k0 + hk);
      __syncthreads();
      As[hk+0][hm]=av.x; As[hk+1][hm]=av.y; As[hk+2][hm]=av.z; As[hk+3][hm]=av.w;
      Bs[hk+0][hm]=bw.x; Bs[hk+1][hm]=bw.y; Bs[hk+2][hm]=bw.z; Bs[hk+3][hm]=bw.w;
      __syncthreads();
      #pragma unroll
      for (int k=0;k<8;k++){
        float a[8], b[8];
        *(float4*)&a[0] = *(const float4*)&As[k][ty*8];
        *(float4*)&a[4] = *(const float4*)&As[k][ty*8+4];
        *(float4*)&b[0] = *(const float4*)&Bs[k][tx*8];
        *(float4*)&b[4] = *(const float4*)&Bs[k][tx*8+4];
        #pragma unroll
        for (int i=0;i<8;i++)
          #pragma unroll
          for (int j=0;j<8;j++)
            acc[i][j] += a[i]*b[j];
      }
    }
    // online softmax merge for this 128-wide r-chunk
    #pragma unroll
    for (int i=0;i<8;i++){
      float sc[8]; float cmax=-1e30f;
      #pragma unroll
      for (int j=0;j<8;j++){ sc[j]=acc[i][j]*scl + ms[tx*8+j]; cmax=fmaxf(cmax,sc[j]); }
      #pragma unroll
      for (int o=8;o>0;o>>=1) cmax = fmaxf(cmax, __shfl_xor_sync(0xffffffffu,cmax,o));
      float nm   = fmaxf(row_m[i], cmax);
      float corr = __expf(row_m[i]-nm);
      float ps=0.f, pa=0.f;
      #pragma unroll
      for (int j=0;j<8;j++){
        float e = __expf(sc[j]-nm);
        ps += e; pa += e*v1s[tx*8+j];
      }
      #pragma unroll
      for (int o=8;o>0;o>>=1){
        ps += __shfl_xor_sync(0xffffffffu,ps,o);
        pa += __shfl_xor_sync(0xffffffffu,pa,o);
      }
      row_s[i] = row_s[i]*corr + ps;
      row_a[i] = row_a[i]*corr + pa;
      row_m[i] = nm;
    }
  }
  if (tx==0){
    float b0 = bdp[0];
    #pragma unroll
    for (int i=0;i<8;i++){
      int fs = m0 + ty*8 + i;
      int f = fs >> 9, s = fs & 511;
      g_laws2[((size_t)f*LC + l)*SEQm + s] = row_a[i]/row_s[i] + b0;
    }
  }
}

// ---------------- scores2[f,l] = laws2[f,l,:] . w_lawprob + b_lawprob ----------------
__global__ void scores2_kernel(const float* __restrict__ wlp, const float* __restrict__ blp){
  int row = (blockIdx.x*blockDim.x + threadIdx.x) >> 5;
  if (row >= 2*LC) return;
  int lane = threadIdx.x & 31;
  const float* p = g_laws2 + (size_t)row*SEQm;
  float s=0.f;
  for (int k=lane;k<SEQm;k+=32) s += p[k]*wlp[k];
  s = warp_sum(s);
  if (!lane) g_scores2[row] = s + blp[0];
}

// ---------------- small heads: law, argmax, law_language_pred, accu, term ----------------
__global__ void head_kernel(const float* __restrict__ output,
                            const float* __restrict__ laws_table,
                            const float* __restrict__ W_law,  const float* __restrict__ b_law,
                            const float* __restrict__ W_rule, const float* __restrict__ b_rule,
                            const float* __restrict__ W_fact, const float* __restrict__ b_fact,
                            const float* __restrict__ W_accu, const float* __restrict__ b_accu,
                            const float* __restrict__ W_term, const float* __restrict__ b_term,
                            float* __restrict__ out){
  __shared__ float cls_s[2][Dm];
  __shared__ float law0_s[2][LC];
  __shared__ float law_s[2][LC];
  __shared__ int   lawno_s[2];
  int tid = threadIdx.x;
  for (int i=tid;i<2*Dm;i+=256)
    cls_s[i/Dm][i%Dm] = output[(size_t)(i/Dm)*SEQm*Dm + (i%Dm)];
  __syncthreads();
  // law0 (-> smem), accu (-> out[206..444)), term (-> out[444..466))
  for (int job=tid;job<206+2*ACLS+2*TCLS;job+=256){
    if (job<206){
      int f=job/LC, c=job%LC;
      float s=0.f;
      for (int d=0;d<Dm;d++) s += cls_s[f][d]*W_law[(size_t)d*LC+c];
      law0_s[f][c] = s + b_law[c];
    } else if (job<206+2*ACLS){
      int q=job-206; int f=q/ACLS, c=q%ACLS;
      float s=0.f;
      for (int d=0;d<Dm;d++) s += cls_s[f][d]*W_accu[(size_t)d*ACLS+c];
      out[206+q] = s + b_accu[c];
    } else {
      int q=job-(206+2*ACLS); int f=q/TCLS, c=q%TCLS;
      float s=0.f;
      for (int d=0;d<Dm;d++) s += cls_s[f][d]*W_term[(size_t)d*TCLS+c];
      out[206+2*ACLS+q] = s + b_term[c];
    }
  }
  __syncthreads();
  // law = law0 @ W_rulelaw + b_rulelaw + scores2 @ W_factlaw + b_factlaw  -> out[0..206)
  for (int job=tid;job<2*LC;job+=256){
    int f=job/LC, c=job%LC;
    float s = b_rule[c] + b_fact[c];
    for (int j=0;j<LC;j++)
      s += law0_s[f][j]*W_rule[(size_t)j*LC+c] + g_scores2[f*LC+j]*W_fact[(size_t)j*LC+c];
    law_s[f][c]=s;
    out[job]=s;
  }
  __syncthreads();
  if (tid<2){
    int best=0; float bvv=law_s[tid][0];
    for (int c=1;c<LC;c++) if (law_s[tid][c]>bvv){ bvv=law_s[tid][c]; best=c; }
    lawno_s[tid]=best;
    out[2*LC+2*ACLS+2*TCLS+2*LC+tid] = (float)best;   // out[672+tid]
  }
  __syncthreads();
  // law_language_pred = laws_table[law_no] @ W_law + b_law  -> out[466..672)
  for (int job=tid;job<2*LC;job+=256){
    int f=job/LC, c=job%LC;
    const float* lb = laws_table + (size_t)lawno_s[f]*Dm;
    float s=0.f;
    for (int d=0;d<Dm;d++) s += lb[d]*W_law[(size_t)d*LC+c];
    out[2*LC+2*ACLS+2*TCLS+job] = s + b_law[c];
  }
}

// ---------------- launch ----------------
extern "C" void kernel_launch(void* const* d_in, const int* in_sizes, int n_in,
                              void* d_out, int out_size){
  const float* output     = (const float*)d_in[0];
  const float* fact_emb   = (const float*)d_in[1];
  const float* law_embs   = (const float*)d_in[2];
  const float* law_masks  = (const float*)d_in[3];
  const float* laws_table = (const float*)d_in[4];
  const float* Wq  = (const float*)d_in[5];
  const float* bq  = (const float*)d_in[6];
  const float* Wk  = (const float*)d_in[7];
  // d_in[8] = bk : softmax-invariant, provably drops out
  const float* Wv  = (const float*)d_in[9];
  const float* bv  = (const float*)d_in[10];
  const float* w_dprob   = (const float*)d_in[11];
  const float* b_dprob   = (const float*)d_in[12];
  const float* w_lawprob = (const float*)d_in[13];
  const float* b_lawprob = (const float*)d_in[14];
  const float* W_rulelaw = (const float*)d_in[15];
  const float* b_rulelaw = (const float*)d_in[16];
  const float* W_factlaw = (const float*)d_in[17];
  const float* b_factlaw = (const float*)d_in[18];
  const float* W_law = (const float*)d_in[19];
  const float* b_law = (const float*)d_in[20];
  const float* W_accu = (const float*)d_in[21];
  const float* b_accu = (const float*)d_in[22];
  const float* W_term = (const float*)d_in[23];
  const float* b_term = (const float*)d_in[24];
  float* out = (float*)d_out;

  void *pM=nullptr, *pT=nullptr, *pTb=nullptr;
  cudaGetSymbolAddress(&pM,  g_M);
  cudaGetSymbolAddress(&pT,  g_t);
  cudaGetSymbolAddress(&pTb, g_tbias);

  prep_kernel<<<193,256>>>(Wk, bq, Wv, w_dprob, bv);
  gemm128<true ><<<dim3(Dm/128, Dm/128),256>>>(Wq, Wk, (float*)pM, Dm, Dm, Dm, nullptr);
  gemm128<false><<<dim3(NFS/128, Dm/128),256>>>(fact_emb, (const float*)pM, (float*)pT,
                                                NFS, Dm, Dm, (const float*)pTb);
  v1_kernel<<<(LC*SEQm + 7)/8, 256>>>(law_embs);
  attn_kernel<<<dim3(NFS/128, LC),256>>>(law_embs, law_masks, b_dprob);
  scores2_kernel<<<(2*LC + 7)/8, 256>>>(w_lawprob, b_lawprob);
  head_kernel<<<1,256>>>(output, laws_table, W_law, b_law, W_rulelaw, b_rulelaw,
                         W_factlaw, b_factlaw, W_accu, b_accu, W_term, b_term, out);
}

// round 3
// speedup vs baseline: 1.9728x; 1.9728x over previous
#include <cuda_runtime.h>
#include <cuda_bf16.h>
#include <math.h>
#include <cstdint>

#define Dm   768
#define SEQm 512
#define NFS  1024   // B(2) * S(512)
#define LC   103
#define ACLS 119
#define TCLS 11

// ---------------- scratch (static device globals; no allocation) ----------------
__device__ float g_M[Dm*Dm];        // Wq @ Wk^T
__device__ float g_t[NFS*Dm];       // fact_emb @ M + Wk@bq
__device__ float g_wv1[Dm];         // Wv @ w_dprob
__device__ float g_tbias[Dm];       // Wk @ bq
__device__ float g_cbv;             // bv . w_dprob
__device__ float g_v1[LC*SEQm];     // law_embs . wv1 + cbv
__device__ float g_laws2[2*LC*SEQm];
__device__ float g_scores2[2*LC];
__device__ __nv_bfloat16 g_t_hi[NFS*Dm];
__device__ __nv_bfloat16 g_t_lo[NFS*Dm];
__device__ __nv_bfloat16 g_y_hi[(size_t)LC*SEQm*Dm];
__device__ __nv_bfloat16 g_y_lo[(size_t)LC*SEQm*Dm];

__device__ __forceinline__ float warp_sum(float s){
  #pragma unroll
  for (int o=16;o>0;o>>=1) s += __shfl_xor_sync(0xffffffffu, s, o);
  return s;
}

__device__ __forceinline__ uint32_t smem_u32(const void* p){
  uint32_t a;
  asm("{ .reg .u64 t; cvta.to.shared.u64 t, %1; cvt.u32.u64 %0, t; }" : "=r"(a) : "l"(p));
  return a;
}

// ---------------- cp.async helpers ----------------
__device__ __forceinline__ void cp16(uint32_t dst, const void* src){
  asm volatile("cp.async.cg.shared.global [%0], [%1], 16;" :: "r"(dst), "l"(src) : "memory");
}
__device__ __forceinline__ void cp_commit(){ asm volatile("cp.async.commit_group;" ::: "memory"); }
template<int N> __device__ __forceinline__ void cp_wait(){ asm volatile("cp.async.wait_group %0;" :: "n"(N) : "memory"); }

#define LDSM4(r0,r1,r2,r3,addr) \
  asm volatile("ldmatrix.sync.aligned.m8n8.x4.shared.b16 {%0,%1,%2,%3}, [%4];" \
    : "=r"(r0), "=r"(r1), "=r"(r2), "=r"(r3) : "r"(addr))

__device__ __forceinline__ void mma16816(float* c, uint32_t a0, uint32_t a1, uint32_t a2, uint32_t a3,
                                         uint32_t b0, uint32_t b1){
  asm volatile("mma.sync.aligned.m16n8k16.row.col.f32.bf16.bf16.f32 "
    "{%0,%1,%2,%3}, {%4,%5,%6,%7}, {%8,%9}, {%0,%1,%2,%3};"
    : "+f"(c[0]), "+f"(c[1]), "+f"(c[2]), "+f"(c[3])
    : "r"(a0), "r"(a1), "r"(a2), "r"(a3), "r"(b0), "r"(b1));
}

// ---------------- small precompute: wv1, tbias, cbv ----------------
__global__ void prep_kernel(const float* __restrict__ Wk, const float* __restrict__ bq,
                            const float* __restrict__ Wv, const float* __restrict__ wd,
                            const float* __restrict__ bv){
  int warp = (blockIdx.x*blockDim.x + threadIdx.x) >> 5;
  int lane = threadIdx.x & 31;
  if (warp < Dm){
    const float* row = Wv + (size_t)warp*Dm;
    float s=0.f;
    for (int k=lane;k<Dm;k+=32) s += row[k]*wd[k];
    s = warp_sum(s);
    if (!lane) g_wv1[warp]=s;
  } else if (warp < 2*Dm){
    int n = warp - Dm;
    const float* row = Wk + (size_t)n*Dm;
    float s=0.f;
    for (int k=lane;k<Dm;k+=32) s += row[k]*bq[k];
    s = warp_sum(s);
    if (!lane) g_tbias[n]=s;
  } else if (warp == 2*Dm){
    float s=0.f;
    for (int k=lane;k<Dm;k+=32) s += bv[k]*wd[k];
    s = warp_sum(s);
    if (!lane) g_cbv=s;
  }
}

// ---------------- 128x128x8 fp32 tiled GEMM ----------------
template<bool TRANSB>
__global__ void __launch_bounds__(256) gemm128(const float* __restrict__ A,
                                               const float* __restrict__ B,
                                               float* __restrict__ C,
                                               int M, int N, int K,
                                               const float* __restrict__ bias){
  __shared__ float As[8][132];
  __shared__ float Bs[8][132];
  int m0 = blockIdx.x*128, n0 = blockIdx.y*128;
  int tid = threadIdx.x;
  int tx = tid & 15, ty = tid >> 4;
  int hm = tid >> 1, hk = (tid & 1)*4;
  float acc[8][8];
  #pragma unroll
  for (int i=0;i<8;i++)
    #pragma unroll
    for (int j=0;j<8;j++) acc[i][j]=0.f;

  for (int k0=0;k0<K;k0+=8){
    float4 av = *(const float4*)(A + (size_t)(m0+hm)*K + k0 + hk);
    float4 bw;
    if (TRANSB) bw = *(const float4*)(B + (size_t)(n0+hm)*K + k0 + hk);
    else        bw = *(const float4*)(B + (size_t)(k0 + (tid>>5))*N + n0 + (tid&31)*4);
    __syncthreads();
    As[hk+0][hm]=av.x; As[hk+1][hm]=av.y; As[hk+2][hm]=av.z; As[hk+3][hm]=av.w;
    if (TRANSB){ Bs[hk+0][hm]=bw.x; Bs[hk+1][hm]=bw.y; Bs[hk+2][hm]=bw.z; Bs[hk+3][hm]=bw.w; }
    else       { *(float4*)&Bs[tid>>5][(tid&31)*4] = bw; }
    __syncthreads();
    #pragma unroll
    for (int k=0;k<8;k++){
      float a[8], b[8];
      *(float4*)&a[0] = *(const float4*)&As[k][ty*8];
      *(float4*)&a[4] = *(const float4*)&As[k][ty*8+4];
      *(float4*)&b[0] = *(const float4*)&Bs[k][tx*8];
      *(float4*)&b[4] = *(const float4*)&Bs[k][tx*8+4];
      #pragma unroll
      for (int i=0;i<8;i++)
        #pragma unroll
        for (int j=0;j<8;j++)
          acc[i][j] += a[i]*b[j];
    }
  }
  #pragma unroll
  for (int i=0;i<8;i++){
    size_t row = (size_t)(m0 + ty*8 + i);
    #pragma unroll
    for (int j=0;j<8;j+=4){
      int col = n0 + tx*8 + j;
      float4 v = make_float4(acc[i][j], acc[i][j+1], acc[i][j+2], acc[i][j+3]);
      if (bias){ v.x+=bias[col]; v.y+=bias[col+1]; v.z+=bias[col+2]; v.w+=bias[col+3]; }
      *(float4*)(C + row*N + col) = v;
    }
  }
}

// ---------------- t -> hi/lo bf16 ----------------
__global__ void conv_t_kernel(){
  int i = blockIdx.x*blockDim.x + threadIdx.x;
  if (i >= NFS*Dm/4) return;
  float4 v = *((const float4*)g_t + i);
  float f[4] = {v.x, v.y, v.z, v.w};
  __nv_bfloat16 h[4], lo[4];
  #pragma unroll
  for (int k=0;k<4;k++){
    h[k]  = __float2bfloat16_rn(f[k]);
    lo[k] = __float2bfloat16_rn(f[k] - __bfloat162float(h[k]));
  }
  __nv_bfloat162 h01, h23, l01, l23;
  h01.x=h[0]; h01.y=h[1]; h23.x=h[2]; h23.y=h[3];
  l01.x=lo[0]; l01.y=lo[1]; l23.x=lo[2]; l23.y=lo[3];
  ((__nv_bfloat162*)g_t_hi)[2*i]   = h01;
  ((__nv_bfloat162*)g_t_hi)[2*i+1] = h23;
  ((__nv_bfloat162*)g_t_lo)[2*i]   = l01;
  ((__nv_bfloat162*)g_t_lo)[2*i+1] = l23;
}

// ---------------- v1 + law_embs -> hi/lo bf16 (one streaming pass) ----------------
__global__ void v1y_kernel(const float* __restrict__ y){
  int row = (blockIdx.x*blockDim.x + threadIdx.x) >> 5;
  if (row >= LC*SEQm) return;
  int lane = threadIdx.x & 31;
  const float4* p = (const float4*)(y + (size_t)row*Dm);
  __nv_bfloat162* oh = (__nv_bfloat162*)(g_y_hi + (size_t)row*Dm);
  __nv_bfloat162* ol = (__nv_bfloat162*)(g_y_lo + (size_t)row*Dm);
  float s = 0.f;
  #pragma unroll
  for (int k=lane;k<Dm/4;k+=32){
    float4 a = p[k];
    float4 w = *(const float4*)(g_wv1 + 4*k);
    s += a.x*w.x + a.y*w.y + a.z*w.z + a.w*w.w;
    float f[4] = {a.x,a.y,a.z,a.w};
    __nv_bfloat16 h[4], lo[4];
    #pragma unroll
    for (int q=0;q<4;q++){
      h[q]  = __float2bfloat16_rn(f[q]);
      lo[q] = __float2bfloat16_rn(f[q] - __bfloat162float(h[q]));
    }
    __nv_bfloat162 h01,h23,l01,l23;
    h01.x=h[0]; h01.y=h[1]; h23.x=h[2]; h23.y=h[3];
    l01.x=lo[0]; l01.y=lo[1]; l23.x=lo[2]; l23.y=lo[3];
    oh[2*k]=h01; oh[2*k+1]=h23;
    ol[2*k]=l01; ol[2*k+1]=l23;
  }
  s = warp_sum(s);
  if (!lane) g_v1[row] = s + g_cbv;
}

// ---------------- fused mma.sync attention ----------------
// Per CTA: l = blockIdx.y, 128 fs-rows at m0 = blockIdx.x*128.
// S[128,512] in 4 n-chunks of 128 via split-bf16 HMMA (3 products), online
// softmax per row, scalar-V accumulation. Tiles padded to 72 bf16/row.
#define TPAD 72
#define TILE_B (128*TPAD*2)          // 18432
#define STAGE_B (4*TILE_B)           // 73728
#define SM_S    (2*STAGE_B)          // 147456
#define SM_V1   (SM_S + 128*133*4)   // +68096 = 215552
#define SM_MS   (SM_V1 + 512)
#define SM_PM   (SM_MS + 512)
#define SM_PS   (SM_PM + 1024)
#define SM_PA   (SM_PS + 1024)
#define ATTN_SMEM (SM_PA + 1024)     // 219648

__global__ void __launch_bounds__(256,1)
attn_mma_kernel(const float* __restrict__ mask, const float* __restrict__ bdp){
  extern __shared__ char smem[];
  const uint32_t sb = smem_u32(smem);
  const int tid = threadIdx.x;
  const int lane = tid & 31, wid = tid >> 5;
  const int l = blockIdx.y, m0 = blockIdx.x*128;
  const int warpM = (wid >> 1)*32;
  const int warpN = (wid & 1)*64;

  float* S   = (float*)(smem + SM_S);
  float* v1s = (float*)(smem + SM_V1);
  float* ms  = (float*)(smem + SM_MS);
  float* pm  = (float*)(smem + SM_PM);
  float* ps  = (float*)(smem + SM_PS);
  float* pa  = (float*)(smem + SM_PA);

  const __nv_bfloat16* yl_hi = g_y_hi + (size_t)l*SEQm*Dm;
  const __nv_bfloat16* yl_lo = g_y_lo + (size_t)l*SEQm*Dm;
  const __nv_bfloat16* a_hi  = g_t_hi + (size_t)m0*Dm;
  const __nv_bfloat16* a_lo  = g_t_lo + (size_t)m0*Dm;

  // per-thread copy indices: 4 rows x 16B per tile
  const int cpRow  = tid >> 3;          // 0..31 base row (advance by 32)
  const int cpColE = (tid & 7)*8;       // bf16 element col (16B chunk)
  // ldmatrix lane addressing
  const uint32_t aOff = (uint32_t)((warpM + (lane & 15))*(TPAD*2) + (8*(lane >> 4))*2);
  const uint32_t bOff = (uint32_t)((warpN + 8*((lane >> 4) & 1) + (lane & 7))*(TPAD*2) + (8*((lane >> 3) & 1))*2);

  const float scl = 0.03608439182435161f;   // 1/sqrt(768)
  float row_m = -1e30f, row_s = 0.f, row_a = 0.f;

  for (int nc=0; nc<4; nc++){
    const int n0 = nc*128;
    __syncthreads();
    if (tid < 128){
      v1s[tid] = g_v1[l*SEQm + n0 + tid];
      ms[tid]  = mask[l*SEQm + n0 + tid];
    }

    float acc[2][8][4];
    #pragma unroll
    for (int mt=0;mt<2;mt++)
      #pragma unroll
      for (int nt=0;nt<8;nt++)
        #pragma unroll
        for (int q=0;q<4;q++) acc[mt][nt][q]=0.f;

    // load one k-chunk (4 tiles of 128x64) into a stage
    auto load_chunk = [&](int stage, int k0){
      uint32_t st = sb + stage*STAGE_B;
      #pragma unroll
      for (int i=0;i<4;i++){
        int row = cpRow + i*32;
        uint32_t so = (uint32_t)(row*(TPAD*2) + cpColE*2);
        size_t go = (size_t)row*Dm + k0 + cpColE;
        size_t gy = (size_t)(n0+row)*Dm + k0 + cpColE;
        cp16(st + 0*TILE_B + so, a_hi + go);
        cp16(st + 1*TILE_B + so, a_lo + go);
        cp16(st + 2*TILE_B + so, yl_hi + gy);
        cp16(st + 3*TILE_B + so, yl_lo + gy);
      }
      cp_commit();
    };

    load_chunk(0, 0);
    for (int kc=0; kc<12; kc++){
      if (kc < 11) load_chunk((kc+1)&1, (kc+1)*64);
      if (kc < 11) cp_wait<1>(); else cp_wait<0>();
      __syncthreads();
      uint32_t st = sb + (kc&1)*STAGE_B;
      uint32_t tAh = st, tAl = st + TILE_B, tBh = st + 2*TILE_B, tBl = st + 3*TILE_B;
      #pragma unroll
      for (int kk=0; kk<4; kk++){
        uint32_t ko = kk*32;   // 16 bf16 = 32 bytes
        uint32_t ah[2][4], al[2][4], bh[4][4], bl[4][4];
        #pragma unroll
        for (int mt=0; mt<2; mt++){
          LDSM4(ah[mt][0],ah[mt][1],ah[mt][2],ah[mt][3], tAh + aOff + mt*(16*TPAD*2) + ko);
          LDSM4(al[mt][0],al[mt][1],al[mt][2],al[mt][3], tAl + aOff + mt*(16*TPAD*2) + ko);
        }
        #pragma unroll
        for (int p=0; p<4; p++){
          LDSM4(bh[p][0],bh[p][1],bh[p][2],bh[p][3], tBh + bOff + p*(16*TPAD*2) + ko);
          LDSM4(bl[p][0],bl[p][1],bl[p][2],bl[p][3], tBl + bOff + p*(16*TPAD*2) + ko);
        }
        #pragma unroll
        for (int mt=0; mt<2; mt++)
          #pragma unroll
          for (int nt=0; nt<8; nt++){
            int p = nt >> 1, pr = (nt & 1)*2;
            mma16816(acc[mt][nt], ah[mt][0],ah[mt][1],ah[mt][2],ah[mt][3], bh[p][pr], bh[p][pr+1]);
            mma16816(acc[mt][nt], ah[mt][0],ah[mt][1],ah[mt][2],ah[mt][3], bl[p][pr], bl[p][pr+1]);
            mma16816(acc[mt][nt], al[mt][0],al[mt][1],al[mt][2],al[mt][3], bh[p][pr], bh[p][pr+1]);
          }
      }
      __syncthreads();
    }

    // dump S (raw scores) to smem, padded stride 133
    {
      int r0 = warpM + (lane >> 2);
      int c0 = warpN + 2*(lane & 3);
      #pragma unroll
      for (int mt=0; mt<2; mt++)
        #pragma unroll
        for (int nt=0; nt<8; nt++){
          int rr = r0 + 16*mt, cc = c0 + 8*nt;
          S[rr*133 + cc]     = acc[mt][nt][0];
          S[rr*133 + cc + 1] = acc[mt][nt][1];
          S[(rr+8)*133 + cc]     = acc[mt][nt][2];
          S[(rr+8)*133 + cc + 1] = acc[mt][nt][3];
        }
    }
    __syncthreads();

    // half-row softmax pass: thread = (row r, half h)
    {
      int r = tid & 127, h = tid >> 7;
      const float* Srow = S + r*133 + h*64;
      const float* mh = ms + h*64;
      const float* vh = v1s + h*64;
      float mx = -1e30f;
      #pragma unroll 4
      for (int c=0;c<64;c++) mx = fmaxf(mx, Srow[c]*scl + mh[c]);
      float ssum=0.f, asum=0.f;
      #pragma unroll 4
      for (int c=0;c<64;c++){
        float e = __expf(Srow[c]*scl + mh[c] - mx);
        ssum += e; asum += e*vh[c];
      }
      pm[h*128+r]=mx; ps[h*128+r]=ssum; pa[h*128+r]=asum;
    }
    __syncthreads();
    if (tid < 128){
      int r = tid;
      float m0h=pm[r], m1h=pm[128+r];
      float m01 = fmaxf(m0h, m1h);
      float s01 = ps[r]*__expf(m0h-m01) + ps[128+r]*__expf(m1h-m01);
      float a01 = pa[r]*__expf(m0h-m01) + pa[128+r]*__expf(m1h-m01);
      float nm = fmaxf(row_m, m01);
      float c1 = __expf(row_m-nm), c2 = __expf(m01-nm);
      row_s = row_s*c1 + s01*c2;
      row_a = row_a*c1 + a01*c2;
      row_m = nm;
    }
  }

  if (tid < 128){
    int fs = m0 + tid;
    int f = fs >> 9, si = fs & 511;
    g_laws2[((size_t)f*LC + l)*SEQm + si] = row_a/row_s + bdp[0];
  }
}

// ---------------- scores2[f,l] = laws2[f,l,:] . w_lawprob + b_lawprob ----------------
__global__ void scores2_kernel(const float* __restrict__ wlp, const float* __restrict__ blp){
  int row = (blockIdx.x*blockDim.x + threadIdx.x) >> 5;
  if (row >= 2*LC) return;
  int lane = threadIdx.x & 31;
  const float* p = g_laws2 + (size_t)row*SEQm;
  float s=0.f;
  for (int k=lane;k<SEQm;k+=32) s += p[k]*wlp[k];
  s = warp_sum(s);
  if (!lane) g_scores2[row] = s + blp[0];
}

// ---------------- small heads ----------------
__global__ void head_kernel(const float* __restrict__ output,
                            const float* __restrict__ laws_table,
                            const float* __restrict__ W_law,  const float* __restrict__ b_law,
                            const float* __restrict__ W_rule, const float* __restrict__ b_rule,
                            const float* __restrict__ W_fact, const float* __restrict__ b_fact,
                            const float* __restrict__ W_accu, const float* __restrict__ b_accu,
                            const float* __restrict__ W_term, const float* __restrict__ b_term,
                            float* __restrict__ out){
  __shared__ float cls_s[2][Dm];
  __shared__ float law0_s[2][LC];
  __shared__ float law_s[2][LC];
  __shared__ int   lawno_s[2];
  int tid = threadIdx.x;
  for (int i=tid;i<2*Dm;i+=256)
    cls_s[i/Dm][i%Dm] = output[(size_t)(i/Dm)*SEQm*Dm + (i%Dm)];
  __syncthreads();
  for (int job=tid;job<206+2*ACLS+2*TCLS;job+=256){
    if (job<206){
      int f=job/LC, c=job%LC;
      float s=0.f;
      for (int d=0;d<Dm;d++) s += cls_s[f][d]*W_law[(size_t)d*LC+c];
      law0_s[f][c] = s + b_law[c];
    } else if (job<206+2*ACLS){
      int q=job-206; int f=q/ACLS, c=q%ACLS;
      float s=0.f;
      for (int d=0;d<Dm;d++) s += cls_s[f][d]*W_accu[(size_t)d*ACLS+c];
      out[206+q] = s + b_accu[c];
    } else {
      int q=job-(206+2*ACLS); int f=q/TCLS, c=q%TCLS;
      float s=0.f;
      for (int d=0;d<Dm;d++) s += cls_s[f][d]*W_term[(size_t)d*TCLS+c];
      out[206+2*ACLS+q] = s + b_term[c];
    }
  }
  __syncthreads();
  for (int job=tid;job<2*LC;job+=256){
    int f=job/LC, c=job%LC;
    float s = b_rule[c] + b_fact[c];
    for (int j=0;j<LC;j++)
      s += law0_s[f][j]*W_rule[(size_t)j*LC+c] + g_scores2[f*LC+j]*W_fact[(size_t)j*LC+c];
    law_s[f][c]=s;
    out[job]=s;
  }
  __syncthreads();
  if (tid<2){
    int best=0; float bvv=law_s[tid][0];
    for (int c=1;c<LC;c++) if (law_s[tid][c]>bvv){ bvv=law_s[tid][c]; best=c; }
    lawno_s[tid]=best;
    out[2*LC+2*ACLS+2*TCLS+2*LC+tid] = (float)best;
  }
  __syncthreads();
  for (int job=tid;job<2*LC;job+=256){
    int f=job/LC, c=job%LC;
    const float* lb = laws_table + (size_t)lawno_s[f]*Dm;
    float s=0.f;
    for (int d=0;d<Dm;d++) s += lb[d]*W_law[(size_t)d*LC+c];
    out[2*LC+2*ACLS+2*TCLS+job] = s + b_law[c];
  }
}

// ---------------- launch ----------------
extern "C" void kernel_launch(void* const* d_in, const int* in_sizes, int n_in,
                              void* d_out, int out_size){
  const float* output     = (const float*)d_in[0];
  const float* fact_emb   = (const float*)d_in[1];
  const float* law_embs   = (const float*)d_in[2];
  const float* law_masks  = (const float*)d_in[3];
  const float* laws_table = (const float*)d_in[4];
  const float* Wq  = (const float*)d_in[5];
  const float* bq  = (const float*)d_in[6];
  const float* Wk  = (const float*)d_in[7];
  // d_in[8] = bk : softmax-invariant, drops out
  const float* Wv  = (const float*)d_in[9];
  const float* bv  = (const float*)d_in[10];
  const float* w_dprob   = (const float*)d_in[11];
  const float* b_dprob   = (const float*)d_in[12];
  const float* w_lawprob = (const float*)d_in[13];
  const float* b_lawprob = (const float*)d_in[14];
  const float* W_rulelaw = (const float*)d_in[15];
  const float* b_rulelaw = (const float*)d_in[16];
  const float* W_factlaw = (const float*)d_in[17];
  const float* b_factlaw = (const float*)d_in[18];
  const float* W_law = (const float*)d_in[19];
  const float* b_law = (const float*)d_in[20];
  const float* W_accu = (const float*)d_in[21];
  const float* b_accu = (const float*)d_in[22];
  const float* W_term = (const float*)d_in[23];
  const float* b_term = (const float*)d_in[24];
  float* out = (float*)d_out;

  void *pM=nullptr, *pT=nullptr, *pTb=nullptr;
  cudaGetSymbolAddress(&pM,  g_M);
  cudaGetSymbolAddress(&pT,  g_t);
  cudaGetSymbolAddress(&pTb, g_tbias);

  cudaFuncSetAttribute(attn_mma_kernel, cudaFuncAttributeMaxDynamicSharedMemorySize, ATTN_SMEM);

  prep_kernel<<<193,256>>>(Wk, bq, Wv, w_dprob, bv);
  gemm128<true ><<<dim3(Dm/128, Dm/128),256>>>(Wq, Wk, (float*)pM, Dm, Dm, Dm, nullptr);
  gemm128<false><<<dim3(NFS/128, Dm/128),256>>>(fact_emb, (const float*)pM, (float*)pT,
                                                NFS, Dm, Dm, (const float*)pTb);
  conv_t_kernel<<<(NFS*Dm/4 + 255)/256, 256>>>();
  v1y_kernel<<<(LC*SEQm + 7)/8, 256>>>(law_embs);
  attn_mma_kernel<<<dim3(NFS/128, LC), 256, ATTN_SMEM>>>(law_masks, b_dprob);
  scores2_kernel<<<(2*LC + 7)/8, 256>>>(w_lawprob, b_lawprob);
  head_kernel<<<1,256>>>(output, laws_table, W_law, b_law, W_rulelaw, b_rulelaw,
                         W_factlaw, b_factlaw, W_accu, b_accu, W_term, b_term, out);
}

// round 4
// speedup vs baseline: 2.8940x; 1.4670x over previous
#include <cuda_runtime.h>
#include <cuda_bf16.h>
#include <cuda_fp16.h>
#include <math.h>
#include <cstdint>

#define Dm   768
#define SEQm 512
#define NFS  1024   // B(2) * S(512)
#define LC   103
#define ACLS 119
#define TCLS 11

// ---------------- scratch (static device globals; no allocation) ----------------
__device__ float g_M[Dm*Dm];        // Wq @ Wk^T
__device__ float g_t[NFS*Dm];       // fact_emb @ M + Wk@bq
__device__ float g_wv1[Dm];         // Wv @ w_dprob
__device__ float g_tbias[Dm];       // Wk @ bq
__device__ float g_cbv;             // bv . w_dprob
__device__ float g_v1[LC*SEQm];     // law_embs . wv1 + cbv
__device__ float g_laws2[2*LC*SEQm];
__device__ float g_scores2[2*LC];
__device__ __half g_t_f16[NFS*Dm];
__device__ __half g_y_f16[(size_t)LC*SEQm*Dm];

__device__ __forceinline__ float warp_sum(float s){
  #pragma unroll
  for (int o=16;o>0;o>>=1) s += __shfl_xor_sync(0xffffffffu, s, o);
  return s;
}

__device__ __forceinline__ uint32_t smem_u32(const void* p){
  uint32_t a;
  asm("{ .reg .u64 t; cvta.to.shared.u64 t, %1; cvt.u32.u64 %0, t; }" : "=r"(a) : "l"(p));
  return a;
}

// ---------------- cp.async helpers ----------------
__device__ __forceinline__ void cp16(uint32_t dst, const void* src){
  asm volatile("cp.async.cg.shared.global [%0], [%1], 16;" :: "r"(dst), "l"(src) : "memory");
}
__device__ __forceinline__ void cp_commit(){ asm volatile("cp.async.commit_group;" ::: "memory"); }
template<int N> __device__ __forceinline__ void cp_wait(){ asm volatile("cp.async.wait_group %0;" :: "n"(N) : "memory"); }

#define LDSM4(r0,r1,r2,r3,addr) \
  asm volatile("ldmatrix.sync.aligned.m8n8.x4.shared.b16 {%0,%1,%2,%3}, [%4];" \
    : "=r"(r0), "=r"(r1), "=r"(r2), "=r"(r3) : "r"(addr))

__device__ __forceinline__ void mma16816(float* c, uint32_t a0, uint32_t a1, uint32_t a2, uint32_t a3,
                                         uint32_t b0, uint32_t b1){
  asm volatile("mma.sync.aligned.m16n8k16.row.col.f32.f16.f16.f32 "
    "{%0,%1,%2,%3}, {%4,%5,%6,%7}, {%8,%9}, {%0,%1,%2,%3};"
    : "+f"(c[0]), "+f"(c[1]), "+f"(c[2]), "+f"(c[3])
    : "r"(a0), "r"(a1), "r"(a2), "r"(a3), "r"(b0), "r"(b1));
}

// ---------------- small precompute: wv1, tbias, cbv ----------------
__global__ void prep_kernel(const float* __restrict__ Wk, const float* __restrict__ bq,
                            const float* __restrict__ Wv, const float* __restrict__ wd,
                            const float* __restrict__ bv){
  int warp = (blockIdx.x*blockDim.x + threadIdx.x) >> 5;
  int lane = threadIdx.x & 31;
  if (warp < Dm){
    const float* row = Wv + (size_t)warp*Dm;
    float s=0.f;
    for (int k=lane;k<Dm;k+=32) s += row[k]*wd[k];
    s = warp_sum(s);
    if (!lane) g_wv1[warp]=s;
  } else if (warp < 2*Dm){
    int n = warp - Dm;
    const float* row = Wk + (size_t)n*Dm;
    float s=0.f;
    for (int k=lane;k<Dm;k+=32) s += row[k]*bq[k];
    s = warp_sum(s);
    if (!lane) g_tbias[n]=s;
  } else if (warp == 2*Dm){
    float s=0.f;
    for (int k=lane;k<Dm;k+=32) s += bv[k]*wd[k];
    s = warp_sum(s);
    if (!lane) g_cbv=s;
  }
}

// ---------------- 128x128x8 fp32 tiled GEMM ----------------
template<bool TRANSB>
__global__ void __launch_bounds__(256) gemm128(const float* __restrict__ A,
                                               const float* __restrict__ B,
                                               float* __restrict__ C,
                                               int M, int N, int K,
                                               const float* __restrict__ bias){
  __shared__ float As[8][132];
  __shared__ float Bs[8][132];
  int m0 = blockIdx.x*128, n0 = blockIdx.y*128;
  int tid = threadIdx.x;
  int tx = tid & 15, ty = tid >> 4;
  int hm = tid >> 1, hk = (tid & 1)*4;
  float acc[8][8];
  #pragma unroll
  for (int i=0;i<8;i++)
    #pragma unroll
    for (int j=0;j<8;j++) acc[i][j]=0.f;

  for (int k0=0;k0<K;k0+=8){
    float4 av = *(const float4*)(A + (size_t)(m0+hm)*K + k0 + hk);
    float4 bw;
    if (TRANSB) bw = *(const float4*)(B + (size_t)(n0+hm)*K + k0 + hk);
    else        bw = *(const float4*)(B + (size_t)(k0 + (tid>>5))*N + n0 + (tid&31)*4);
    __syncthreads();
    As[hk+0][hm]=av.x; As[hk+1][hm]=av.y; As[hk+2][hm]=av.z; As[hk+3][hm]=av.w;
    if (TRANSB){ Bs[hk+0][hm]=bw.x; Bs[hk+1][hm]=bw.y; Bs[hk+2][hm]=bw.z; Bs[hk+3][hm]=bw.w; }
    else       { *(float4*)&Bs[tid>>5][(tid&31)*4] = bw; }
    __syncthreads();
    #pragma unroll
    for (int k=0;k<8;k++){
      float a[8], b[8];
      *(float4*)&a[0] = *(const float4*)&As[k][ty*8];
      *(float4*)&a[4] = *(const float4*)&As[k][ty*8+4];
      *(float4*)&b[0] = *(const float4*)&Bs[k][tx*8];
      *(float4*)&b[4] = *(const float4*)&Bs[k][tx*8+4];
      #pragma unroll
      for (int i=0;i<8;i++)
        #pragma unroll
        for (int j=0;j<8;j++)
          acc[i][j] += a[i]*b[j];
    }
  }
  #pragma unroll
  for (int i=0;i<8;i++){
    size_t row = (size_t)(m0 + ty*8 + i);
    #pragma unroll
    for (int j=0;j<8;j+=4){
      int col = n0 + tx*8 + j;
      float4 v = make_float4(acc[i][j], acc[i][j+1], acc[i][j+2], acc[i][j+3]);
      if (bias){ v.x+=bias[col]; v.y+=bias[col+1]; v.z+=bias[col+2]; v.w+=bias[col+3]; }
      *(float4*)(C + row*N + col) = v;
    }
  }
}

// ---------------- t -> fp16 ----------------
__global__ void conv_t_kernel(){
  int i = blockIdx.x*blockDim.x + threadIdx.x;
  if (i >= NFS*Dm/4) return;
  float4 v = *((const float4*)g_t + i);
  __half2 h01, h23;
  h01 = __floats2half2_rn(v.x, v.y);
  h23 = __floats2half2_rn(v.z, v.w);
  ((__half2*)g_t_f16)[2*i]   = h01;
  ((__half2*)g_t_f16)[2*i+1] = h23;
}

// ---------------- v1 + law_embs -> fp16 (one streaming pass) ----------------
__global__ void v1y_kernel(const float* __restrict__ y){
  int row = (blockIdx.x*blockDim.x + threadIdx.x) >> 5;
  if (row >= LC*SEQm) return;
  int lane = threadIdx.x & 31;
  const float4* p = (const float4*)(y + (size_t)row*Dm);
  __half2* oh = (__half2*)(g_y_f16 + (size_t)row*Dm);
  float s = 0.f;
  #pragma unroll
  for (int k=lane;k<Dm/4;k+=32){
    float4 a = p[k];
    float4 w = *(const float4*)(g_wv1 + 4*k);
    s += a.x*w.x + a.y*w.y + a.z*w.z + a.w*w.w;
    oh[2*k]   = __floats2half2_rn(a.x, a.y);
    oh[2*k+1] = __floats2half2_rn(a.z, a.w);
  }
  s = warp_sum(s);
  if (!lane) g_v1[row] = s + g_cbv;
}

// ---------------- fused mma.sync attention (fp16 single-product) ----------------
// Per CTA: l = blockIdx.y, 128 fs-rows at m0 = blockIdx.x*128.
// S[128,512] in 4 n-chunks of 128, 3-stage cp.async pipeline over 12 k-chunks
// of 64, online softmax per row, scalar-V accumulation.
#define TPAD 72
#define TILE_B (128*TPAD*2)          // 18432
#define STAGE_B (2*TILE_B)           // 36864 (A tile + B tile)
#define SM_S    (3*STAGE_B)          // 110592
#define SM_V1   (SM_S + 128*133*4)   // 178688
#define SM_MS   (SM_V1 + 512)
#define SM_PM   (SM_MS + 512)
#define SM_PS   (SM_PM + 1024)
#define SM_PA   (SM_PS + 1024)
#define ATTN_SMEM (SM_PA + 1024)     // 182784

__global__ void __launch_bounds__(256,1)
attn_mma_kernel(const float* __restrict__ mask, const float* __restrict__ bdp){
  extern __shared__ char smem[];
  const uint32_t sb = smem_u32(smem);
  const int tid = threadIdx.x;
  const int lane = tid & 31, wid = tid >> 5;
  const int l = blockIdx.y, m0 = blockIdx.x*128;
  const int warpM = (wid >> 1)*32;
  const int warpN = (wid & 1)*64;

  float* S   = (float*)(smem + SM_S);
  float* v1s = (float*)(smem + SM_V1);
  float* ms  = (float*)(smem + SM_MS);
  float* pm  = (float*)(smem + SM_PM);
  float* ps  = (float*)(smem + SM_PS);
  float* pa  = (float*)(smem + SM_PA);

  const __half* yl_f = g_y_f16 + (size_t)l*SEQm*Dm;
  const __half* a_f  = g_t_f16 + (size_t)m0*Dm;

  const int cpRow  = tid >> 3;          // 0..31 base row (advance by 32)
  const int cpColE = (tid & 7)*8;       // fp16 element col (16B chunk)
  const uint32_t aOff = (uint32_t)((warpM + (lane & 15))*(TPAD*2) + (8*(lane >> 4))*2);
  const uint32_t bOff = (uint32_t)((warpN + 8*((lane >> 4) & 1) + (lane & 7))*(TPAD*2) + (8*((lane >> 3) & 1))*2);

  const float scl = 0.03608439182435161f;   // 1/sqrt(768)
  float row_m = -1e30f, row_s = 0.f, row_a = 0.f;

  for (int nc=0; nc<4; nc++){
    const int n0 = nc*128;
    __syncthreads();
    if (tid < 128){
      v1s[tid] = g_v1[l*SEQm + n0 + tid];
      ms[tid]  = mask[l*SEQm + n0 + tid];
    }

    float acc[2][8][4];
    #pragma unroll
    for (int mt=0;mt<2;mt++)
      #pragma unroll
      for (int nt=0;nt<8;nt++)
        #pragma unroll
        for (int q=0;q<4;q++) acc[mt][nt][q]=0.f;

    auto load_chunk = [&](int stage, int k0){
      uint32_t st = sb + stage*STAGE_B;
      #pragma unroll
      for (int i=0;i<4;i++){
        int row = cpRow + i*32;
        uint32_t so = (uint32_t)(row*(TPAD*2) + cpColE*2);
        cp16(st + so,          a_f  + (size_t)row*Dm + k0 + cpColE);
        cp16(st + TILE_B + so, yl_f + (size_t)(n0+row)*Dm + k0 + cpColE);
      }
      cp_commit();
    };

    load_chunk(0, 0);
    load_chunk(1, 64);
    int stage = 0, ldst = 2;
    #pragma unroll 1
    for (int kc=0; kc<12; kc++){
      if (kc < 10) load_chunk(ldst, (kc+2)*64);
      else         cp_commit();                 // empty group keeps wait<2> semantics
      if (++ldst == 3) ldst = 0;
      cp_wait<2>();
      __syncthreads();
      uint32_t st = sb + stage*STAGE_B;
      if (++stage == 3) stage = 0;
      uint32_t tA = st, tB = st + TILE_B;
      #pragma unroll
      for (int kk=0; kk<4; kk++){
        uint32_t ko = kk*32;   // 16 fp16 = 32 bytes
        uint32_t ah[2][4], bh[4][4];
        #pragma unroll
        for (int mt=0; mt<2; mt++)
          LDSM4(ah[mt][0],ah[mt][1],ah[mt][2],ah[mt][3], tA + aOff + mt*(16*TPAD*2) + ko);
        #pragma unroll
        for (int p=0; p<4; p++)
          LDSM4(bh[p][0],bh[p][1],bh[p][2],bh[p][3], tB + bOff + p*(16*TPAD*2) + ko);
        #pragma unroll
        for (int mt=0; mt<2; mt++)
          #pragma unroll
          for (int nt=0; nt<8; nt++){
            int p = nt >> 1, pr = (nt & 1)*2;
            mma16816(acc[mt][nt], ah[mt][0],ah[mt][1],ah[mt][2],ah[mt][3], bh[p][pr], bh[p][pr+1]);
          }
      }
      __syncthreads();
    }

    // dump S (raw scores) to smem, padded stride 133
    {
      int r0 = warpM + (lane >> 2);
      int c0 = warpN + 2*(lane & 3);
      #pragma unroll
      for (int mt=0; mt<2; mt++)
        #pragma unroll
        for (int nt=0; nt<8; nt++){
          int rr = r0 + 16*mt, cc = c0 + 8*nt;
          S[rr*133 + cc]     = acc[mt][nt][0];
          S[rr*133 + cc + 1] = acc[mt][nt][1];
          S[(rr+8)*133 + cc]     = acc[mt][nt][2];
          S[(rr+8)*133 + cc + 1] = acc[mt][nt][3];
        }
    }
    __syncthreads();

    // half-row softmax pass: thread = (row r, half h)
    {
      int r = tid & 127, h = tid >> 7;
      const float* Srow = S + r*133 + h*64;
      const float* mh = ms + h*64;
      const float* vh = v1s + h*64;
      float mx = -1e30f;
      #pragma unroll 4
      for (int c=0;c<64;c++) mx = fmaxf(mx, Srow[c]*scl + mh[c]);
      float ssum=0.f, asum=0.f;
      #pragma unroll 4
      for (int c=0;c<64;c++){
        float e = __expf(Srow[c]*scl + mh[c] - mx);
        ssum += e; asum += e*vh[c];
      }
      pm[h*128+r]=mx; ps[h*128+r]=ssum; pa[h*128+r]=asum;
    }
    __syncthreads();
    if (tid < 128){
      int r = tid;
      float m0h=pm[r], m1h=pm[128+r];
      float m01 = fmaxf(m0h, m1h);
      float s01 = ps[r]*__expf(m0h-m01) + ps[128+r]*__expf(m1h-m01);
      float a01 = pa[r]*__expf(m0h-m01) + pa[128+r]*__expf(m1h-m01);
      float nm = fmaxf(row_m, m01);
      float c1 = __expf(row_m-nm), c2 = __expf(m01-nm);
      row_s = row_s*c1 + s01*c2;
      row_a = row_a*c1 + a01*c2;
      row_m = nm;
    }
  }

  if (tid < 128){
    int fs = m0 + tid;
    int f = fs >> 9, si = fs & 511;
    g_laws2[((size_t)f*LC + l)*SEQm + si] = row_a/row_s + bdp[0];
  }
}

// ---------------- scores2[f,l] = laws2[f,l,:] . w_lawprob + b_lawprob ----------------
__global__ void scores2_kernel(const float* __restrict__ wlp, const float* __restrict__ blp){
  int row = (blockIdx.x*blockDim.x + threadIdx.x) >> 5;
  if (row >= 2*LC) return;
  int lane = threadIdx.x & 31;
  const float* p = g_laws2 + (size_t)row*SEQm;
  float s=0.f;
  for (int k=lane;k<SEQm;k+=32) s += p[k]*wlp[k];
  s = warp_sum(s);
  if (!lane) g_scores2[row] = s + blp[0];
}

// ---------------- small heads ----------------
__global__ void head_kernel(const float* __restrict__ output,
                            const float* __restrict__ laws_table,
                            const float* __restrict__ W_law,  const float* __restrict__ b_law,
                            const float* __restrict__ W_rule, const float* __restrict__ b_rule,
                            const float* __restrict__ W_fact, const float* __restrict__ b_fact,
                            const float* __restrict__ W_accu, const float* __restrict__ b_accu,
                            const float* __restrict__ W_term, const float* __restrict__ b_term,
                            float* __restrict__ out){
  __shared__ float cls_s[2][Dm];
  __shared__ float law0_s[2][LC];
  __shared__ float law_s[2][LC];
  __shared__ int   lawno_s[2];
  int tid = threadIdx.x;
  for (int i=tid;i<2*Dm;i+=256)
    cls_s[i/Dm][i%Dm] = output[(size_t)(i/Dm)*SEQm*Dm + (i%Dm)];
  __syncthreads();
  for (int job=tid;job<206+2*ACLS+2*TCLS;job+=256){
    if (job<206){
      int f=job/LC, c=job%LC;
      float s=0.f;
      for (int d=0;d<Dm;d++) s += cls_s[f][d]*W_law[(size_t)d*LC+c];
      law0_s[f][c] = s + b_law[c];
    } else if (job<206+2*ACLS){
      int q=job-206; int f=q/ACLS, c=q%ACLS;
      float s=0.f;
      for (int d=0;d<Dm;d++) s += cls_s[f][d]*W_accu[(size_t)d*ACLS+c];
      out[206+q] = s + b_accu[c];
    } else {
      int q=job-(206+2*ACLS); int f=q/TCLS, c=q%TCLS;
      float s=0.f;
      for (int d=0;d<Dm;d++) s += cls_s[f][d]*W_term[(size_t)d*TCLS+c];
      out[206+2*ACLS+q] = s + b_term[c];
    }
  }
  __syncthreads();
  for (int job=tid;job<2*LC;job+=256){
    int f=job/LC, c=job%LC;
    float s = b_rule[c] + b_fact[c];
    for (int j=0;j<LC;j++)
      s += law0_s[f][j]*W_rule[(size_t)j*LC+c] + g_scores2[f*LC+j]*W_fact[(size_t)j*LC+c];
    law_s[f][c]=s;
    out[job]=s;
  }
  __syncthreads();
  if (tid<2){
    int best=0; float bvv=law_s[tid][0];
    for (int c=1;c<LC;c++) if (law_s[tid][c]>bvv){ bvv=law_s[tid][c]; best=c; }
    lawno_s[tid]=best;
    out[2*LC+2*ACLS+2*TCLS+2*LC+tid] = (float)best;
  }
  __syncthreads();
  for (int job=tid;job<2*LC;job+=256){
    int f=job/LC, c=job%LC;
    const float* lb = laws_table + (size_t)lawno_s[f]*Dm;
    float s=0.f;
    for (int d=0;d<Dm;d++) s += lb[d]*W_law[(size_t)d*LC+c];
    out[2*LC+2*ACLS+2*TCLS+job] = s + b_law[c];
  }
}

// ---------------- launch ----------------
extern "C" void kernel_launch(void* const* d_in, const int* in_sizes, int n_in,
                              void* d_out, int out_size){
  const float* output     = (const float*)d_in[0];
  const float* fact_emb   = (const float*)d_in[1];
  const float* law_embs   = (const float*)d_in[2];
  const float* law_masks  = (const float*)d_in[3];
  const float* laws_table = (const float*)d_in[4];
  const float* Wq  = (const float*)d_in[5];
  const float* bq  = (const float*)d_in[6];
  const float* Wk  = (const float*)d_in[7];
  // d_in[8] = bk : softmax-invariant, drops out
  const float* Wv  = (const float*)d_in[9];
  const float* bv  = (const float*)d_in[10];
  const float* w_dprob   = (const float*)d_in[11];
  const float* b_dprob   = (const float*)d_in[12];
  const float* w_lawprob = (const float*)d_in[13];
  const float* b_lawprob = (const float*)d_in[14];
  const float* W_rulelaw = (const float*)d_in[15];
  const float* b_rulelaw = (const float*)d_in[16];
  const float* W_factlaw = (const float*)d_in[17];
  const float* b_factlaw = (const float*)d_in[18];
  const float* W_law = (const float*)d_in[19];
  const float* b_law = (const float*)d_in[20];
  const float* W_accu = (const float*)d_in[21];
  const float* b_accu = (const float*)d_in[22];
  const float* W_term = (const float*)d_in[23];
  const float* b_term = (const float*)d_in[24];
  float* out = (float*)d_out;

  void *pM=nullptr, *pT=nullptr, *pTb=nullptr;
  cudaGetSymbolAddress(&pM,  g_M);
  cudaGetSymbolAddress(&pT,  g_t);
  cudaGetSymbolAddress(&pTb, g_tbias);

  cudaFuncSetAttribute(attn_mma_kernel, cudaFuncAttributeMaxDynamicSharedMemorySize, ATTN_SMEM);

  prep_kernel<<<193,256>>>(Wk, bq, Wv, w_dprob, bv);
  gemm128<true ><<<dim3(Dm/128, Dm/128),256>>>(Wq, Wk, (float*)pM, Dm, Dm, Dm, nullptr);
  gemm128<false><<<dim3(NFS/128, Dm/128),256>>>(fact_emb, (const float*)pM, (float*)pT,
                                                NFS, Dm, Dm, (const float*)pTb);
  conv_t_kernel<<<(NFS*Dm/4 + 255)/256, 256>>>();
  v1y_kernel<<<(LC*SEQm + 7)/8, 256>>>(law_embs);
  attn_mma_kernel<<<dim3(NFS/128, LC), 256, ATTN_SMEM>>>(law_masks, b_dprob);
  scores2_kernel<<<(2*LC + 7)/8, 256>>>(w_lawprob, b_lawprob);
  head_kernel<<<1,256>>>(output, laws_table, W_law, b_law, W_rulelaw, b_rulelaw,
                         W_factlaw, b_factlaw, W_accu, b_accu, W_term, b_term, out);
}

// round 5
// speedup vs baseline: 3.2963x; 1.1390x over previous
#include <cuda_runtime.h>
#include <cuda_bf16.h>
#include <cuda_fp16.h>
#include <math.h>
#include <cstdint>

#define Dm   768
#define SEQm 512
#define NFS  1024   // B(2) * S(512)
#define LC   103
#define ACLS 119
#define TCLS 11

// ---------------- scratch (static device globals; no allocation) ----------------
__device__ float g_M[Dm*Dm];        // Wq @ Wk^T
__device__ float g_t[NFS*Dm];       // fact_emb @ M + Wk@bq
__device__ float g_wv1[Dm];         // Wv @ w_dprob
__device__ float g_tbias[Dm];       // Wk @ bq
__device__ float g_cbv;             // bv . w_dprob
__device__ float g_v1[LC*SEQm];     // law_embs . wv1 + cbv
__device__ float g_laws2[2*LC*SEQm];
__device__ float g_scores2[2*LC];
__device__ __half g_t_f16[NFS*Dm];
__device__ __half g_y_f16[(size_t)LC*SEQm*Dm];

__device__ __forceinline__ float warp_sum(float s){
  #pragma unroll
  for (int o=16;o>0;o>>=1) s += __shfl_xor_sync(0xffffffffu, s, o);
  return s;
}

__device__ __forceinline__ uint32_t smem_u32(const void* p){
  uint32_t a;
  asm("{ .reg .u64 t; cvta.to.shared.u64 t, %1; cvt.u32.u64 %0, t; }" : "=r"(a) : "l"(p));
  return a;
}

// ---------------- cp.async helpers ----------------
__device__ __forceinline__ void cp16(uint32_t dst, const void* src){
  asm volatile("cp.async.cg.shared.global [%0], [%1], 16;" :: "r"(dst), "l"(src) : "memory");
}
__device__ __forceinline__ void cp_commit(){ asm volatile("cp.async.commit_group;" ::: "memory"); }
template<int N> __device__ __forceinline__ void cp_wait(){ asm volatile("cp.async.wait_group %0;" :: "n"(N) : "memory"); }

#define LDSM4(r0,r1,r2,r3,addr) \
  asm volatile("ldmatrix.sync.aligned.m8n8.x4.shared.b16 {%0,%1,%2,%3}, [%4];" \
    : "=r"(r0), "=r"(r1), "=r"(r2), "=r"(r3) : "r"(addr))

__device__ __forceinline__ void mma16816(float* c, uint32_t a0, uint32_t a1, uint32_t a2, uint32_t a3,
                                         uint32_t b0, uint32_t b1){
  asm volatile("mma.sync.aligned.m16n8k16.row.col.f32.f16.f16.f32 "
    "{%0,%1,%2,%3}, {%4,%5,%6,%7}, {%8,%9}, {%0,%1,%2,%3};"
    : "+f"(c[0]), "+f"(c[1]), "+f"(c[2]), "+f"(c[3])
    : "r"(a0), "r"(a1), "r"(a2), "r"(a3), "r"(b0), "r"(b1));
}

// ---------------- small precompute: wv1, tbias, cbv ----------------
__global__ void prep_kernel(const float* __restrict__ Wk, const float* __restrict__ bq,
                            const float* __restrict__ Wv, const float* __restrict__ wd,
                            const float* __restrict__ bv){
  int warp = (blockIdx.x*blockDim.x + threadIdx.x) >> 5;
  int lane = threadIdx.x & 31;
  if (warp < Dm){
    const float* row = Wv + (size_t)warp*Dm;
    float s=0.f;
    for (int k=lane;k<Dm;k+=32) s += row[k]*wd[k];
    s = warp_sum(s);
    if (!lane) g_wv1[warp]=s;
  } else if (warp < 2*Dm){
    int n = warp - Dm;
    const float* row = Wk + (size_t)n*Dm;
    float s=0.f;
    for (int k=lane;k<Dm;k+=32) s += row[k]*bq[k];
    s = warp_sum(s);
    if (!lane) g_tbias[n]=s;
  } else if (warp == 2*Dm){
    float s=0.f;
    for (int k=lane;k<Dm;k+=32) s += bv[k]*wd[k];
    s = warp_sum(s);
    if (!lane) g_cbv=s;
  }
}

// ---------------- 128x128x8 fp32 tiled GEMM ----------------
template<bool TRANSB>
__global__ void __launch_bounds__(256) gemm128(const float* __restrict__ A,
                                               const float* __restrict__ B,
                                               float* __restrict__ C,
                                               int M, int N, int K,
                                               const float* __restrict__ bias){
  __shared__ float As[8][132];
  __shared__ float Bs[8][132];
  int m0 = blockIdx.x*128, n0 = blockIdx.y*128;
  int tid = threadIdx.x;
  int tx = tid & 15, ty = tid >> 4;
  int hm = tid >> 1, hk = (tid & 1)*4;
  float acc[8][8];
  #pragma unroll
  for (int i=0;i<8;i++)
    #pragma unroll
    for (int j=0;j<8;j++) acc[i][j]=0.f;

  for (int k0=0;k0<K;k0+=8){
    float4 av = *(const float4*)(A + (size_t)(m0+hm)*K + k0 + hk);
    float4 bw;
    if (TRANSB) bw = *(const float4*)(B + (size_t)(n0+hm)*K + k0 + hk);
    else        bw = *(const float4*)(B + (size_t)(k0 + (tid>>5))*N + n0 + (tid&31)*4);
    __syncthreads();
    As[hk+0][hm]=av.x; As[hk+1][hm]=av.y; As[hk+2][hm]=av.z; As[hk+3][hm]=av.w;
    if (TRANSB){ Bs[hk+0][hm]=bw.x; Bs[hk+1][hm]=bw.y; Bs[hk+2][hm]=bw.z; Bs[hk+3][hm]=bw.w; }
    else       { *(float4*)&Bs[tid>>5][(tid&31)*4] = bw; }
    __syncthreads();
    #pragma unroll
    for (int k=0;k<8;k++){
      float a[8], b[8];
      *(float4*)&a[0] = *(const float4*)&As[k][ty*8];
      *(float4*)&a[4] = *(const float4*)&As[k][ty*8+4];
      *(float4*)&b[0] = *(const float4*)&Bs[k][tx*8];
      *(float4*)&b[4] = *(const float4*)&Bs[k][tx*8+4];
      #pragma unroll
      for (int i=0;i<8;i++)
        #pragma unroll
        for (int j=0;j<8;j++)
          acc[i][j] += a[i]*b[j];
    }
  }
  #pragma unroll
  for (int i=0;i<8;i++){
    size_t row = (size_t)(m0 + ty*8 + i);
    #pragma unroll
    for (int j=0;j<8;j+=4){
      int col = n0 + tx*8 + j;
      float4 v = make_float4(acc[i][j], acc[i][j+1], acc[i][j+2], acc[i][j+3]);
      if (bias){ v.x+=bias[col]; v.y+=bias[col+1]; v.z+=bias[col+2]; v.w+=bias[col+3]; }
      *(float4*)(C + row*N + col) = v;
    }
  }
}

// ---------------- t -> fp16 ----------------
__global__ void conv_t_kernel(){
  int i = blockIdx.x*blockDim.x + threadIdx.x;
  if (i >= NFS*Dm/4) return;
  float4 v = *((const float4*)g_t + i);
  __half2 h01, h23;
  h01 = __floats2half2_rn(v.x, v.y);
  h23 = __floats2half2_rn(v.z, v.w);
  ((__half2*)g_t_f16)[2*i]   = h01;
  ((__half2*)g_t_f16)[2*i+1] = h23;
}

// ---------------- v1 + law_embs -> fp16 (one streaming pass) ----------------
__global__ void v1y_kernel(const float* __restrict__ y){
  int row = (blockIdx.x*blockDim.x + threadIdx.x) >> 5;
  if (row >= LC*SEQm) return;
  int lane = threadIdx.x & 31;
  const float4* p = (const float4*)(y + (size_t)row*Dm);
  __half2* oh = (__half2*)(g_y_f16 + (size_t)row*Dm);
  float s = 0.f;
  #pragma unroll
  for (int k=lane;k<Dm/4;k+=32){
    float4 a = p[k];
    float4 w = *(const float4*)(g_wv1 + 4*k);
    s += a.x*w.x + a.y*w.y + a.z*w.z + a.w*w.w;
    oh[2*k]   = __floats2half2_rn(a.x, a.y);
    oh[2*k+1] = __floats2half2_rn(a.z, a.w);
  }
  s = warp_sum(s);
  if (!lane) g_v1[row] = s + g_cbv;
}

// ---------------- fused mma.sync attention (fp16, register softmax, occ=2) ----------------
#define TPAD 72
#define TILE_B (128*TPAD*2)          // 18432
#define STAGE_B (2*TILE_B)           // 36864 (A tile + B tile)
#define SM_V1   (2*STAGE_B)          // 73728
#define SM_MS   (SM_V1 + 512)
#define SM_PM   (SM_MS + 512)        // float[2][128]
#define SM_PS   (SM_PM + 1024)
#define SM_PA   (SM_PS + 1024)
#define ATTN_SMEM (SM_PA + 1024)     // 77824

__global__ void __launch_bounds__(256,2)
attn_mma_kernel(const float* __restrict__ mask, const float* __restrict__ bdp){
  extern __shared__ char smem[];
  const uint32_t sb = smem_u32(smem);
  const int tid = threadIdx.x;
  const int lane = tid & 31, wid = tid >> 5;
  const int l = blockIdx.y, m0 = blockIdx.x*128;
  const int warpM = (wid >> 1)*32;
  const int warpN = (wid & 1)*64;

  float* v1s = (float*)(smem + SM_V1);
  float* ms  = (float*)(smem + SM_MS);
  float* pm  = (float*)(smem + SM_PM);
  float* ps  = (float*)(smem + SM_PS);
  float* pa  = (float*)(smem + SM_PA);

  const __half* yl_f = g_y_f16 + (size_t)l*SEQm*Dm;
  const __half* a_f  = g_t_f16 + (size_t)m0*Dm;

  const int cpRow  = tid >> 3;          // 0..31 base row (advance by 32)
  const int cpColE = (tid & 7)*8;       // fp16 element col (16B chunk)
  const uint32_t aOff = (uint32_t)((warpM + (lane & 15))*(TPAD*2) + (8*(lane >> 4))*2);
  const uint32_t bOff = (uint32_t)((warpN + 8*((lane >> 4) & 1) + (lane & 7))*(TPAD*2) + (8*((lane >> 3) & 1))*2);

  const float scl = 0.03608439182435161f;   // 1/sqrt(768)
  float row_m = -1e30f, row_s = 0.f, row_a = 0.f;

  for (int nc=0; nc<4; nc++){
    const int n0 = nc*128;
    __syncthreads();                 // protect v1s/ms/pm/ps/pa vs previous epilogue
    if (tid < 128){
      v1s[tid] = g_v1[l*SEQm + n0 + tid];
      ms[tid]  = mask[l*SEQm + n0 + tid];
    }

    float acc[2][8][4];
    #pragma unroll
    for (int mt=0;mt<2;mt++)
      #pragma unroll
      for (int nt=0;nt<8;nt++)
        #pragma unroll
        for (int q=0;q<4;q++) acc[mt][nt][q]=0.f;

    auto load_chunk = [&](int stage, int k0){
      uint32_t st = sb + stage*STAGE_B;
      #pragma unroll
      for (int i=0;i<4;i++){
        int row = cpRow + i*32;
        uint32_t so = (uint32_t)(row*(TPAD*2) + cpColE*2);
        cp16(st + so,          a_f  + (size_t)row*Dm + k0 + cpColE);
        cp16(st + TILE_B + so, yl_f + (size_t)(n0+row)*Dm + k0 + cpColE);
      }
      cp_commit();
    };

    load_chunk(0, 0);
    load_chunk(1, 64);
    #pragma unroll 1
    for (int kc=0; kc<12; kc++){
      if (kc < 11) cp_wait<1>(); else cp_wait<0>();
      __syncthreads();
      uint32_t st = sb + (kc&1)*STAGE_B;
      uint32_t tA = st, tB = st + TILE_B;
      #pragma unroll
      for (int kk=0; kk<4; kk++){
        uint32_t ko = kk*32;   // 16 fp16 = 32 bytes
        uint32_t ah[2][4];
        #pragma unroll
        for (int mt=0; mt<2; mt++)
          LDSM4(ah[mt][0],ah[mt][1],ah[mt][2],ah[mt][3], tA + aOff + mt*(16*TPAD*2) + ko);
        #pragma unroll
        for (int p=0; p<4; p++){
          uint32_t b0,b1,b2,b3;
          LDSM4(b0,b1,b2,b3, tB + bOff + p*(16*TPAD*2) + ko);
          #pragma unroll
          for (int mt=0; mt<2; mt++){
            mma16816(acc[mt][2*p],   ah[mt][0],ah[mt][1],ah[mt][2],ah[mt][3], b0, b1);
            mma16816(acc[mt][2*p+1], ah[mt][0],ah[mt][1],ah[mt][2],ah[mt][3], b2, b3);
          }
        }
      }
      __syncthreads();
      if (kc < 10) load_chunk(kc&1, (kc+2)*64);
    }

    // ---- register softmax epilogue (no S dump) ----
    {
      const int lq = lane & 3;     // col group within 8
      const int lr = lane >> 2;    // row within 8
      #pragma unroll
      for (int mt=0; mt<2; mt++)
        #pragma unroll
        for (int g=0; g<2; g++){
          float sc[16];
          float mx = -1e30f;
          #pragma unroll
          for (int nt=0; nt<8; nt++)
            #pragma unroll
            for (int p=0; p<2; p++){
              int c = warpN + nt*8 + 2*lq + p;
              float v = acc[mt][nt][g*2+p]*scl + ms[c];
              sc[nt*2+p] = v;
              mx = fmaxf(mx, v);
            }
          mx = fmaxf(mx, __shfl_xor_sync(0xffffffffu, mx, 1));
          mx = fmaxf(mx, __shfl_xor_sync(0xffffffffu, mx, 2));
          float ss = 0.f, aa = 0.f;
          #pragma unroll
          for (int nt=0; nt<8; nt++)
            #pragma unroll
            for (int p=0; p<2; p++){
              int c = warpN + nt*8 + 2*lq + p;
              float e = __expf(sc[nt*2+p] - mx);
              ss += e; aa += e*v1s[c];
            }
          ss += __shfl_xor_sync(0xffffffffu, ss, 1);
          ss += __shfl_xor_sync(0xffffffffu, ss, 2);
          aa += __shfl_xor_sync(0xffffffffu, aa, 1);
          aa += __shfl_xor_sync(0xffffffffu, aa, 2);
          if (lq == 0){
            int row = warpM + mt*16 + g*8 + lr;
            int h = wid & 1;
            pm[h*128+row]=mx; ps[h*128+row]=ss; pa[h*128+row]=aa;
          }
        }
    }
    __syncthreads();
    if (tid < 128){
      int r = tid;
      float m0h=pm[r], m1h=pm[128+r];
      float m01 = fmaxf(m0h, m1h);
      float s01 = ps[r]*__expf(m0h-m01) + ps[128+r]*__expf(m1h-m01);
      float a01 = pa[r]*__expf(m0h-m01) + pa[128+r]*__expf(m1h-m01);
      float nm = fmaxf(row_m, m01);
      float c1 = __expf(row_m-nm), c2 = __expf(m01-nm);
      row_s = row_s*c1 + s01*c2;
      row_a = row_a*c1 + a01*c2;
      row_m = nm;
    }
  }

  if (tid < 128){
    int fs = m0 + tid;
    int f = fs >> 9, si = fs & 511;
    g_laws2[((size_t)f*LC + l)*SEQm + si] = row_a/row_s + bdp[0];
  }
}

// ---------------- scores2[f,l] = laws2[f,l,:] . w_lawprob + b_lawprob ----------------
__global__ void scores2_kernel(const float* __restrict__ wlp, const float* __restrict__ blp){
  int row = (blockIdx.x*blockDim.x + threadIdx.x) >> 5;
  if (row >= 2*LC) return;
  int lane = threadIdx.x & 31;
  const float* p = g_laws2 + (size_t)row*SEQm;
  float s=0.f;
  for (int k=lane;k<SEQm;k+=32) s += p[k]*wlp[k];
  s = warp_sum(s);
  if (!lane) g_scores2[row] = s + blp[0];
}

// ---------------- small heads ----------------
__global__ void head_kernel(const float* __restrict__ output,
                            const float* __restrict__ laws_table,
                            const float* __restrict__ W_law,  const float* __restrict__ b_law,
                            const float* __restrict__ W_rule, const float* __restrict__ b_rule,
                            const float* __restrict__ W_fact, const float* __restrict__ b_fact,
                            const float* __restrict__ W_accu, const float* __restrict__ b_accu,
                            const float* __restrict__ W_term, const float* __restrict__ b_term,
                            float* __restrict__ out){
  __shared__ float cls_s[2][Dm];
  __shared__ float law0_s[2][LC];
  __shared__ float law_s[2][LC];
  __shared__ int   lawno_s[2];
  int tid = threadIdx.x;
  for (int i=tid;i<2*Dm;i+=256)
    cls_s[i/Dm][i%Dm] = output[(size_t)(i/Dm)*SEQm*Dm + (i%Dm)];
  __syncthreads();
  for (int job=tid;job<206+2*ACLS+2*TCLS;job+=256){
    if (job<206){
      int f=job/LC, c=job%LC;
      float s=0.f;
      for (int d=0;d<Dm;d++) s += cls_s[f][d]*W_law[(size_t)d*LC+c];
      law0_s[f][c] = s + b_law[c];
    } else if (job<206+2*ACLS){
      int q=job-206; int f=q/ACLS, c=q%ACLS;
      float s=0.f;
      for (int d=0;d<Dm;d++) s += cls_s[f][d]*W_accu[(size_t)d*ACLS+c];
      out[206+q] = s + b_accu[c];
    } else {
      int q=job-(206+2*ACLS); int f=q/TCLS, c=q%TCLS;
      float s=0.f;
      for (int d=0;d<Dm;d++) s += cls_s[f][d]*W_term[(size_t)d*TCLS+c];
      out[206+2*ACLS+q] = s + b_term[c];
    }
  }
  __syncthreads();
  for (int job=tid;job<2*LC;job+=256){
    int f=job/LC, c=job%LC;
    float s = b_rule[c] + b_fact[c];
    for (int j=0;j<LC;j++)
      s += law0_s[f][j]*W_rule[(size_t)j*LC+c] + g_scores2[f*LC+j]*W_fact[(size_t)j*LC+c];
    law_s[f][c]=s;
    out[job]=s;
  }
  __syncthreads();
  if (tid<2){
    int best=0; float bvv=law_s[tid][0];
    for (int c=1;c<LC;c++) if (law_s[tid][c]>bvv){ bvv=law_s[tid][c]; best=c; }
    lawno_s[tid]=best;
    out[2*LC+2*ACLS+2*TCLS+2*LC+tid] = (float)best;
  }
  __syncthreads();
  for (int job=tid;job<2*LC;job+=256){
    int f=job/LC, c=job%LC;
    const float* lb = laws_table + (size_t)lawno_s[f]*Dm;
    float s=0.f;
    for (int d=0;d<Dm;d++) s += lb[d]*W_law[(size_t)d*LC+c];
    out[2*LC+2*ACLS+2*TCLS+job] = s + b_law[c];
  }
}

// ---------------- launch ----------------
extern "C" void kernel_launch(void* const* d_in, const int* in_sizes, int n_in,
                              void* d_out, int out_size){
  const float* output     = (const float*)d_in[0];
  const float* fact_emb   = (const float*)d_in[1];
  const float* law_embs   = (const float*)d_in[2];
  const float* law_masks  = (const float*)d_in[3];
  const float* laws_table = (const float*)d_in[4];
  const float* Wq  = (const float*)d_in[5];
  const float* bq  = (const float*)d_in[6];
  const float* Wk  = (const float*)d_in[7];
  // d_in[8] = bk : softmax-invariant, drops out
  const float* Wv  = (const float*)d_in[9];
  const float* bv  = (const float*)d_in[10];
  const float* w_dprob   = (const float*)d_in[11];
  const float* b_dprob   = (const float*)d_in[12];
  const float* w_lawprob = (const float*)d_in[13];
  const float* b_lawprob = (const float*)d_in[14];
  const float* W_rulelaw = (const float*)d_in[15];
  const float* b_rulelaw = (const float*)d_in[16];
  const float* W_factlaw = (const float*)d_in[17];
  const float* b_factlaw = (const float*)d_in[18];
  const float* W_law = (const float*)d_in[19];
  const float* b_law = (const float*)d_in[20];
  const float* W_accu = (const float*)d_in[21];
  const float* b_accu = (const float*)d_in[22];
  const float* W_term = (const float*)d_in[23];
  const float* b_term = (const float*)d_in[24];
  float* out = (float*)d_out;

  void *pM=nullptr, *pT=nullptr, *pTb=nullptr;
  cudaGetSymbolAddress(&pM,  g_M);
  cudaGetSymbolAddress(&pT,  g_t);
  cudaGetSymbolAddress(&pTb, g_tbias);

  cudaFuncSetAttribute(attn_mma_kernel, cudaFuncAttributeMaxDynamicSharedMemorySize, ATTN_SMEM);

  prep_kernel<<<193,256>>>(Wk, bq, Wv, w_dprob, bv);
  gemm128<true ><<<dim3(Dm/128, Dm/128),256>>>(Wq, Wk, (float*)pM, Dm, Dm, Dm, nullptr);
  gemm128<false><<<dim3(NFS/128, Dm/128),256>>>(fact_emb, (const float*)pM, (float*)pT,
                                                NFS, Dm, Dm, (const float*)pTb);
  conv_t_kernel<<<(NFS*Dm/4 + 255)/256, 256>>>();
  v1y_kernel<<<(LC*SEQm + 7)/8, 256>>>(law_embs);
  attn_mma_kernel<<<dim3(NFS/128, LC), 256, ATTN_SMEM>>>(law_masks, b_dprob);
  scores2_kernel<<<(2*LC + 7)/8, 256>>>(w_lawprob, b_lawprob);
  head_kernel<<<1,256>>>(output, laws_table, W_law, b_law, W_rulelaw, b_rulelaw,
                         W_factlaw, b_factlaw, W_accu, b_accu, W_term, b_term, out);
}

// round 6
// speedup vs baseline: 3.5652x; 1.0816x over previous
#include <cuda_runtime.h>
#include <cuda_bf16.h>
#include <cuda_fp16.h>
#include <math.h>
#include <cstdint>

#define Dm   768
#define SEQm 512
#define NFS  1024   // B(2) * S(512)
#define LC   103
#define ACLS 119
#define TCLS 11

// ---------------- scratch (static device globals; no allocation) ----------------
__device__ float g_M[Dm*Dm];        // Wq @ Wk^T
__device__ float g_wv1[Dm];         // Wv @ w_dprob
__device__ float g_tbias[Dm];       // Wk @ bq
__device__ float g_cbv;             // bv . w_dprob
__device__ float g_v1[LC*SEQm];     // law_embs . wv1 + cbv
__device__ float g_laws2[2*LC*SEQm];
__device__ float g_scores2[2*LC];
__device__ __half g_t_f16[NFS*Dm];
__device__ __half g_y_f16[(size_t)LC*SEQm*Dm];

__device__ __forceinline__ float warp_sum(float s){
  #pragma unroll
  for (int o=16;o>0;o>>=1) s += __shfl_xor_sync(0xffffffffu, s, o);
  return s;
}

__device__ __forceinline__ uint32_t smem_u32(const void* p){
  uint32_t a;
  asm("{ .reg .u64 t; cvta.to.shared.u64 t, %1; cvt.u32.u64 %0, t; }" : "=r"(a) : "l"(p));
  return a;
}

// ---------------- cp.async helpers ----------------
__device__ __forceinline__ void cp16(uint32_t dst, const void* src){
  asm volatile("cp.async.cg.shared.global [%0], [%1], 16;" :: "r"(dst), "l"(src) : "memory");
}
__device__ __forceinline__ void cp_commit(){ asm volatile("cp.async.commit_group;" ::: "memory"); }
template<int N> __device__ __forceinline__ void cp_wait(){ asm volatile("cp.async.wait_group %0;" :: "n"(N) : "memory"); }

#define LDSM4(r0,r1,r2,r3,addr) \
  asm volatile("ldmatrix.sync.aligned.m8n8.x4.shared.b16 {%0,%1,%2,%3}, [%4];" \
    : "=r"(r0), "=r"(r1), "=r"(r2), "=r"(r3) : "r"(addr))

__device__ __forceinline__ void mma16816(float* c, uint32_t a0, uint32_t a1, uint32_t a2, uint32_t a3,
                                         uint32_t b0, uint32_t b1){
  asm volatile("mma.sync.aligned.m16n8k16.row.col.f32.f16.f16.f32 "
    "{%0,%1,%2,%3}, {%4,%5,%6,%7}, {%8,%9}, {%0,%1,%2,%3};"
    : "+f"(c[0]), "+f"(c[1]), "+f"(c[2]), "+f"(c[3])
    : "r"(a0), "r"(a1), "r"(a2), "r"(a3), "r"(b0), "r"(b1));
}

// ---------------- fused: gemmM (Wq@Wk^T, 36 blocks) + prep (193 blocks) ----------------
__global__ void __launch_bounds__(256) k1_gemmM_prep(const float* __restrict__ Wq,
                                                     const float* __restrict__ Wk,
                                                     const float* __restrict__ bq,
                                                     const float* __restrict__ Wv,
                                                     const float* __restrict__ wd,
                                                     const float* __restrict__ bv){
  if (blockIdx.x < 36){
    // C = Wq @ Wk^T (768x768x768), TRANSB tiles
    __shared__ float As[8][132];
    __shared__ float Bs[8][132];
    int m0 = (blockIdx.x % 6)*128, n0 = (blockIdx.x / 6)*128;
    int tid = threadIdx.x;
    int tx = tid & 15, ty = tid >> 4;
    int hm = tid >> 1, hk = (tid & 1)*4;
    float acc[8][8];
    #pragma unroll
    for (int i=0;i<8;i++)
      #pragma unroll
      for (int j=0;j<8;j++) acc[i][j]=0.f;
    for (int k0=0;k0<Dm;k0+=8){
      float4 av = *(const float4*)(Wq + (size_t)(m0+hm)*Dm + k0 + hk);
      float4 bw = *(const float4*)(Wk + (size_t)(n0+hm)*Dm + k0 + hk);
      __syncthreads();
      As[hk+0][hm]=av.x; As[hk+1][hm]=av.y; As[hk+2][hm]=av.z; As[hk+3][hm]=av.w;
      Bs[hk+0][hm]=bw.x; Bs[hk+1][hm]=bw.y; Bs[hk+2][hm]=bw.z; Bs[hk+3][hm]=bw.w;
      __syncthreads();
      #pragma unroll
      for (int k=0;k<8;k++){
        float a[8], b[8];
        *(float4*)&a[0] = *(const float4*)&As[k][ty*8];
        *(float4*)&a[4] = *(const float4*)&As[k][ty*8+4];
        *(float4*)&b[0] = *(const float4*)&Bs[k][tx*8];
        *(float4*)&b[4] = *(const float4*)&Bs[k][tx*8+4];
        #pragma unroll
        for (int i=0;i<8;i++)
          #pragma unroll
          for (int j=0;j<8;j++)
            acc[i][j] += a[i]*b[j];
      }
    }
    #pragma unroll
    for (int i=0;i<8;i++){
      size_t row = (size_t)(m0 + ty*8 + i);
      #pragma unroll
      for (int j=0;j<8;j+=4)
        *(float4*)(g_M + row*Dm + n0 + tx*8 + j) =
          make_float4(acc[i][j], acc[i][j+1], acc[i][j+2], acc[i][j+3]);
    }
  } else {
    int warp = (blockIdx.x - 36)*8 + (threadIdx.x >> 5);
    int lane = threadIdx.x & 31;
    if (warp < Dm){
      const float* row = Wv + (size_t)warp*Dm;
      float s=0.f;
      for (int k=lane;k<Dm;k+=32) s += row[k]*wd[k];
      s = warp_sum(s);
      if (!lane) g_wv1[warp]=s;
    } else if (warp < 2*Dm){
      int n = warp - Dm;
      const float* row = Wk + (size_t)n*Dm;
      float s=0.f;
      for (int k=lane;k<Dm;k+=32) s += row[k]*bq[k];
      s = warp_sum(s);
      if (!lane) g_tbias[n]=s;
    } else if (warp == 2*Dm){
      float s=0.f;
      for (int k=lane;k<Dm;k+=32) s += bv[k]*wd[k];
      s = warp_sum(s);
      if (!lane) g_cbv=s;
    }
  }
}

// ---------------- t GEMM with fused fp16 output: g_t_f16 = fp16(fact_emb @ M + tbias) ----------------
__global__ void __launch_bounds__(256) gemmT_f16(const float* __restrict__ A){
  __shared__ float As[8][132];
  __shared__ float Bs[8][132];
  int m0 = blockIdx.x*128, n0 = blockIdx.y*128;
  int tid = threadIdx.x;
  int tx = tid & 15, ty = tid >> 4;
  int hm = tid >> 1, hk = (tid & 1)*4;
  float acc[8][8];
  #pragma unroll
  for (int i=0;i<8;i++)
    #pragma unroll
    for (int j=0;j<8;j++) acc[i][j]=0.f;
  for (int k0=0;k0<Dm;k0+=8){
    float4 av = *(const float4*)(A + (size_t)(m0+hm)*Dm + k0 + hk);
    float4 bw = *(const float4*)(g_M + (size_t)(k0 + (tid>>5))*Dm + n0 + (tid&31)*4);
    __syncthreads();
    As[hk+0][hm]=av.x; As[hk+1][hm]=av.y; As[hk+2][hm]=av.z; As[hk+3][hm]=av.w;
    *(float4*)&Bs[tid>>5][(tid&31)*4] = bw;
    __syncthreads();
    #pragma unroll
    for (int k=0;k<8;k++){
      float a[8], b[8];
      *(float4*)&a[0] = *(const float4*)&As[k][ty*8];
      *(float4*)&a[4] = *(const float4*)&As[k][ty*8+4];
      *(float4*)&b[0] = *(const float4*)&Bs[k][tx*8];
      *(float4*)&b[4] = *(const float4*)&Bs[k][tx*8+4];
      #pragma unroll
      for (int i=0;i<8;i++)
        #pragma unroll
        for (int j=0;j<8;j++)
          acc[i][j] += a[i]*b[j];
    }
  }
  #pragma unroll
  for (int i=0;i<8;i++){
    size_t row = (size_t)(m0 + ty*8 + i);
    int col = n0 + tx*8;
    __half2 h[4];
    #pragma unroll
    for (int j=0;j<4;j++)
      h[j] = __floats2half2_rn(acc[i][2*j]   + g_tbias[col+2*j],
                               acc[i][2*j+1] + g_tbias[col+2*j+1]);
    *(uint4*)(g_t_f16 + row*Dm + col) = *(uint4*)h;
  }
}

// ---------------- v1 + law_embs -> fp16 (one streaming pass) ----------------
__global__ void v1y_kernel(const float* __restrict__ y){
  int row = (blockIdx.x*blockDim.x + threadIdx.x) >> 5;
  if (row >= LC*SEQm) return;
  int lane = threadIdx.x & 31;
  const float4* p = (const float4*)(y + (size_t)row*Dm);
  __half2* oh = (__half2*)(g_y_f16 + (size_t)row*Dm);
  float s = 0.f;
  #pragma unroll
  for (int k=lane;k<Dm/4;k+=32){
    float4 a = p[k];
    float4 w = *(const float4*)(g_wv1 + 4*k);
    s += a.x*w.x + a.y*w.y + a.z*w.z + a.w*w.w;
    oh[2*k]   = __floats2half2_rn(a.x, a.y);
    oh[2*k+1] = __floats2half2_rn(a.z, a.w);
  }
  s = warp_sum(s);
  if (!lane) g_v1[row] = s + g_cbv;
}

// ---------------- fused mma.sync attention (swizzled, 3-stage, 1 sync/chunk, occ=2) ----------------
#define TILE_B  16384                 // 128 rows x 128B (64 fp16), SW128-xor swizzled
#define STAGE_B (2*TILE_B)            // 32768 (A tile + B tile)
#define SM_V1   (3*STAGE_B)           // 98304
#define SM_MS   (SM_V1 + 512)
#define SM_PM   (SM_MS + 512)         // float[2][128]
#define SM_PS   (SM_PM + 1024)
#define SM_PA   (SM_PS + 1024)
#define ATTN_SMEM (SM_PA + 1024)      // 102400

__global__ void __launch_bounds__(256,2)
attn_mma_kernel(const float* __restrict__ mask, const float* __restrict__ bdp){
  extern __shared__ char smem[];
  const uint32_t sb = smem_u32(smem);
  const int tid = threadIdx.x;
  const int lane = tid & 31, wid = tid >> 5;
  const int l = blockIdx.y, m0 = blockIdx.x*128;
  const int warpM = (wid >> 1)*32;
  const int warpN = (wid & 1)*64;

  float* v1s = (float*)(smem + SM_V1);
  float* ms  = (float*)(smem + SM_MS);
  float* pm  = (float*)(smem + SM_PM);
  float* ps  = (float*)(smem + SM_PS);
  float* pa  = (float*)(smem + SM_PA);

  const __half* yl_f = g_y_f16 + (size_t)l*SEQm*Dm;
  const __half* a_f  = g_t_f16 + (size_t)m0*Dm;

  // cp.async thread mapping: 4 rows x 16B per tile
  const int cpRow  = tid >> 3;              // base row 0..31 (advance by 32)
  const int cpColE = (tid & 7)*8;           // fp16 element col
  const uint32_t cpColB = (uint32_t)((tid & 7)*16);  // byte col

  // ldmatrix lane addressing (swizzled)
  const int rowA = warpM + (lane & 15);
  const uint32_t rA = (uint32_t)(rowA*128), xA = (uint32_t)((rowA & 7) << 4);
  const uint32_t cA0 = (uint32_t)(16*(lane >> 4));
  const int rowB = warpN + 8*((lane >> 4) & 1) + (lane & 7);
  const uint32_t rB = (uint32_t)(rowB*128), xB = (uint32_t)((rowB & 7) << 4);
  const uint32_t cB0 = (uint32_t)(16*((lane >> 3) & 1));

  const float scl = 0.03608439182435161f;   // 1/sqrt(768)
  float row_m = -1e30f, row_s = 0.f, row_a = 0.f;

  for (int nc=0; nc<4; nc++){
    const int n0 = nc*128;
    __syncthreads();                 // prior epilogue readers done before v1s/ms rewrite
    if (tid < 128){
      v1s[tid] = g_v1[l*SEQm + n0 + tid];
      ms[tid]  = mask[l*SEQm + n0 + tid];
    }

    float acc[2][8][4];
    #pragma unroll
    for (int mt=0;mt<2;mt++)
      #pragma unroll
      for (int nt=0;nt<8;nt++)
        #pragma unroll
        for (int q=0;q<4;q++) acc[mt][nt][q]=0.f;

    auto load_chunk = [&](int slot, int k0){
      uint32_t st = sb + slot*STAGE_B;
      #pragma unroll
      for (int i=0;i<4;i++){
        int row = cpRow + i*32;
        uint32_t so = (uint32_t)(row*128) + (cpColB ^ (uint32_t)((row & 7) << 4));
        cp16(st + so,          a_f  + (size_t)row*Dm + k0 + cpColE);
        cp16(st + TILE_B + so, yl_f + (size_t)(n0+row)*Dm + k0 + cpColE);
      }
      cp_commit();
    };

    load_chunk(0, 0);
    load_chunk(1, 64);
    int ldslot = 2, curslot = 0;
    #pragma unroll 1
    for (int kc=0; kc<12; kc++){
      if (kc < 11) cp_wait<1>(); else cp_wait<0>();
      __syncthreads();
      if (kc < 10){
        load_chunk(ldslot, (kc+2)*64);
        if (++ldslot == 3) ldslot = 0;
      }
      uint32_t st = sb + curslot*STAGE_B;
      if (++curslot == 3) curslot = 0;
      uint32_t tA = st, tB = st + TILE_B;
      #pragma unroll
      for (int kk=0; kk<4; kk++){
        uint32_t cA = (cA0 + kk*32) ^ xA;
        uint32_t cB = (cB0 + kk*32) ^ xB;
        uint32_t ah[2][4];
        #pragma unroll
        for (int mt=0; mt<2; mt++)
          LDSM4(ah[mt][0],ah[mt][1],ah[mt][2],ah[mt][3], tA + rA + mt*2048 + cA);
        #pragma unroll
        for (int p=0; p<4; p++){
          uint32_t b0,b1,b2,b3;
          LDSM4(b0,b1,b2,b3, tB + rB + p*2048 + cB);
          #pragma unroll
          for (int mt=0; mt<2; mt++){
            mma16816(acc[mt][2*p],   ah[mt][0],ah[mt][1],ah[mt][2],ah[mt][3], b0, b1);
            mma16816(acc[mt][2*p+1], ah[mt][0],ah[mt][1],ah[mt][2],ah[mt][3], b2, b3);
          }
        }
      }
    }

    // ---- register softmax epilogue ----
    {
      const int lq = lane & 3;     // col pair within 8
      const int lr = lane >> 2;    // row within 8
      #pragma unroll
      for (int mt=0; mt<2; mt++)
        #pragma unroll
        for (int g=0; g<2; g++){
          float sc[16];
          float mx = -1e30f;
          #pragma unroll
          for (int nt=0; nt<8; nt++)
            #pragma unroll
            for (int p=0; p<2; p++){
              int c = warpN + nt*8 + 2*lq + p;
              float v = acc[mt][nt][g*2+p]*scl + ms[c];
              sc[nt*2+p] = v;
              mx = fmaxf(mx, v);
            }
          mx = fmaxf(mx, __shfl_xor_sync(0xffffffffu, mx, 1));
          mx = fmaxf(mx, __shfl_xor_sync(0xffffffffu, mx, 2));
          float ss = 0.f, aa = 0.f;
          #pragma unroll
          for (int nt=0; nt<8; nt++)
            #pragma unroll
            for (int p=0; p<2; p++){
              int c = warpN + nt*8 + 2*lq + p;
              float e = __expf(sc[nt*2+p] - mx);
              ss += e; aa += e*v1s[c];
            }
          ss += __shfl_xor_sync(0xffffffffu, ss, 1);
          ss += __shfl_xor_sync(0xffffffffu, ss, 2);
          aa += __shfl_xor_sync(0xffffffffu, aa, 1);
          aa += __shfl_xor_sync(0xffffffffu, aa, 2);
          if (lq == 0){
            int row = warpM + mt*16 + g*8 + lr;
            int h = wid & 1;
            pm[h*128+row]=mx; ps[h*128+row]=ss; pa[h*128+row]=aa;
          }
        }
    }
    __syncthreads();
    if (tid < 128){
      int r = tid;
      float m0h=pm[r], m1h=pm[128+r];
      float m01 = fmaxf(m0h, m1h);
      float s01 = ps[r]*__expf(m0h-m01) + ps[128+r]*__expf(m1h-m01);
      float a01 = pa[r]*__expf(m0h-m01) + pa[128+r]*__expf(m1h-m01);
      float nm = fmaxf(row_m, m01);
      float c1 = __expf(row_m-nm), c2 = __expf(m01-nm);
      row_s = row_s*c1 + s01*c2;
      row_a = row_a*c1 + a01*c2;
      row_m = nm;
    }
  }

  if (tid < 128){
    int fs = m0 + tid;
    int f = fs >> 9, si = fs & 511;
    g_laws2[((size_t)f*LC + l)*SEQm + si] = row_a/row_s + bdp[0];
  }
}

// ---------------- head (includes scores2) ----------------
__global__ void head_kernel(const float* __restrict__ output,
                            const float* __restrict__ laws_table,
                            const float* __restrict__ wlp,    const float* __restrict__ blp,
                            const float* __restrict__ W_law,  const float* __restrict__ b_law,
                            const float* __restrict__ W_rule, const float* __restrict__ b_rule,
                            const float* __restrict__ W_fact, const float* __restrict__ b_fact,
                            const float* __restrict__ W_accu, const float* __restrict__ b_accu,
                            const float* __restrict__ W_term, const float* __restrict__ b_term,
                            float* __restrict__ out){
  __shared__ float cls_s[2][Dm];
  __shared__ float law0_s[2][LC];
  __shared__ float law_s[2][LC];
  __shared__ float sc2_s[2*LC];
  __shared__ int   lawno_s[2];
  int tid = threadIdx.x;
  int wid = tid >> 5, lane = tid & 31;

  // scores2[f,l] = laws2[f,l,:] . wlp + blp
  for (int row = wid; row < 2*LC; row += 8){
    const float* p = g_laws2 + (size_t)row*SEQm;
    float s=0.f;
    for (int k=lane;k<SEQm;k+=32) s += p[k]*wlp[k];
    s = warp_sum(s);
    if (!lane) sc2_s[row] = s + blp[0];
  }
  for (int i=tid;i<2*Dm;i+=256)
    cls_s[i/Dm][i%Dm] = output[(size_t)(i/Dm)*SEQm*Dm + (i%Dm)];
  __syncthreads();
  for (int job=tid;job<206+2*ACLS+2*TCLS;job+=256){
    if (job<206){
      int f=job/LC, c=job%LC;
      float s=0.f;
      for (int d=0;d<Dm;d++) s += cls_s[f][d]*W_law[(size_t)d*LC+c];
      law0_s[f][c] = s + b_law[c];
    } else if (job<206+2*ACLS){
      int q=job-206; int f=q/ACLS, c=q%ACLS;
      float s=0.f;
      for (int d=0;d<Dm;d++) s += cls_s[f][d]*W_accu[(size_t)d*ACLS+c];
      out[206+q] = s + b_accu[c];
    } else {
      int q=job-(206+2*ACLS); int f=q/TCLS, c=q%TCLS;
      float s=0.f;
      for (int d=0;d<Dm;d++) s += cls_s[f][d]*W_term[(size_t)d*TCLS+c];
      out[206+2*ACLS+q] = s + b_term[c];
    }
  }
  __syncthreads();
  for (int job=tid;job<2*LC;job+=256){
    int f=job/LC, c=job%LC;
    float s = b_rule[c] + b_fact[c];
    for (int j=0;j<LC;j++)
      s += law0_s[f][j]*W_rule[(size_t)j*LC+c] + sc2_s[f*LC+j]*W_fact[(size_t)j*LC+c];
    law_s[f][c]=s;
    out[job]=s;
  }
  __syncthreads();
  if (tid<2){
    int best=0; float bvv=law_s[tid][0];
    for (int c=1;c<LC;c++) if (law_s[tid][c]>bvv){ bvv=law_s[tid][c]; best=c; }
    lawno_s[tid]=best;
    out[2*LC+2*ACLS+2*TCLS+2*LC+tid] = (float)best;
  }
  __syncthreads();
  for (int job=tid;job<2*LC;job+=256){
    int f=job/LC, c=job%LC;
    const float* lb = laws_table + (size_t)lawno_s[f]*Dm;
    float s=0.f;
    for (int d=0;d<Dm;d++) s += lb[d]*W_law[(size_t)d*LC+c];
    out[2*LC+2*ACLS+2*TCLS+job] = s + b_law[c];
  }
}

// ---------------- launch ----------------
extern "C" void kernel_launch(void* const* d_in, const int* in_sizes, int n_in,
                              void* d_out, int out_size){
  const float* output     = (const float*)d_in[0];
  const float* fact_emb   = (const float*)d_in[1];
  const float* law_embs   = (const float*)d_in[2];
  const float* law_masks  = (const float*)d_in[3];
  const float* laws_table = (const float*)d_in[4];
  const float* Wq  = (const float*)d_in[5];
  const float* bq  = (const float*)d_in[6];
  const float* Wk  = (const float*)d_in[7];
  // d_in[8] = bk : softmax-invariant, drops out
  const float* Wv  = (const float*)d_in[9];
  const float* bv  = (const float*)d_in[10];
  const float* w_dprob   = (const float*)d_in[11];
  const float* b_dprob   = (const float*)d_in[12];
  const float* w_lawprob = (const float*)d_in[13];
  const float* b_lawprob = (const float*)d_in[14];
  const float* W_rulelaw = (const float*)d_in[15];
  const float* b_rulelaw = (const float*)d_in[16];
  const float* W_factlaw = (const float*)d_in[17];
  const float* b_factlaw = (const float*)d_in[18];
  const float* W_law = (const float*)d_in[19];
  const float* b_law = (const float*)d_in[20];
  const float* W_accu = (const float*)d_in[21];
  const float* b_accu = (const float*)d_in[22];
  const float* W_term = (const float*)d_in[23];
  const float* b_term = (const float*)d_in[24];
  float* out = (float*)d_out;

  cudaFuncSetAttribute(attn_mma_kernel, cudaFuncAttributeMaxDynamicSharedMemorySize, ATTN_SMEM);

  k1_gemmM_prep<<<36+193, 256>>>(Wq, Wk, bq, Wv, w_dprob, bv);
  gemmT_f16<<<dim3(NFS/128, Dm/128), 256>>>(fact_emb);
  v1y_kernel<<<(LC*SEQm + 7)/8, 256>>>(law_embs);
  attn_mma_kernel<<<dim3(NFS/128, LC), 256, ATTN_SMEM>>>(law_masks, b_dprob);
  head_kernel<<<1,256>>>(output, laws_table, w_lawprob, b_lawprob,
                         W_law, b_law, W_rulelaw, b_rulelaw,
                         W_factlaw, b_factlaw, W_accu, b_accu, W_term, b_term, out);
}

// round 7
// speedup vs baseline: 4.8469x; 1.3595x over previous
#include <cuda_runtime.h>
#include <cuda_bf16.h>
#include <cuda_fp16.h>
#include <math.h>
#include <cstdint>

#define Dm   768
#define SEQm 512
#define NFS  1024   // B(2) * S(512)
#define LC   103
#define ACLS 119
#define TCLS 11

// ---------------- scratch (static device globals; no allocation) ----------------
__device__ float g_wv1[Dm];         // Wv @ w_dprob
__device__ float g_tbias[Dm];       // Wk @ bq
__device__ float g_cbv;             // bv . w_dprob
__device__ float g_v1[LC*SEQm];     // law_embs . wv1 + cbv
__device__ float g_laws2[2*LC*SEQm];
__device__ __half g_wq16[Dm*Dm];
__device__ __half g_wk16[Dm*Dm];
__device__ __half g_fe16[NFS*Dm];
__device__ __half g_mt16[Dm*Dm];    // MT[j,i] = sum_k Wk[j,k] Wq[i,k]
__device__ __half g_t_f16[NFS*Dm];
__device__ __half g_y_f16[(size_t)LC*SEQm*Dm];

__device__ __forceinline__ float warp_sum(float s){
  #pragma unroll
  for (int o=16;o>0;o>>=1) s += __shfl_xor_sync(0xffffffffu, s, o);
  return s;
}

__device__ __forceinline__ uint32_t smem_u32(const void* p){
  uint32_t a;
  asm("{ .reg .u64 t; cvta.to.shared.u64 t, %1; cvt.u32.u64 %0, t; }" : "=r"(a) : "l"(p));
  return a;
}

// ---------------- cp.async helpers ----------------
__device__ __forceinline__ void cp16(uint32_t dst, const void* src){
  asm volatile("cp.async.cg.shared.global [%0], [%1], 16;" :: "r"(dst), "l"(src) : "memory");
}
__device__ __forceinline__ void cp_commit(){ asm volatile("cp.async.commit_group;" ::: "memory"); }
template<int N> __device__ __forceinline__ void cp_wait(){ asm volatile("cp.async.wait_group %0;" :: "n"(N) : "memory"); }

#define LDSM4(r0,r1,r2,r3,addr) \
  asm volatile("ldmatrix.sync.aligned.m8n8.x4.shared.b16 {%0,%1,%2,%3}, [%4];" \
    : "=r"(r0), "=r"(r1), "=r"(r2), "=r"(r3) : "r"(addr))

__device__ __forceinline__ void mma16816(float* c, uint32_t a0, uint32_t a1, uint32_t a2, uint32_t a3,
                                         uint32_t b0, uint32_t b1){
  asm volatile("mma.sync.aligned.m16n8k16.row.col.f32.f16.f16.f32 "
    "{%0,%1,%2,%3}, {%4,%5,%6,%7}, {%8,%9}, {%0,%1,%2,%3};"
    : "+f"(c[0]), "+f"(c[1]), "+f"(c[2]), "+f"(c[3])
    : "r"(a0), "r"(a1), "r"(a2), "r"(a3), "r"(b0), "r"(b1));
}

// shared tile geometry for all HMMA kernels
#define TILE_B  16384                 // 128 rows x 128B (64 fp16), SW128-xor swizzled
#define STAGE_B (2*TILE_B)            // 32768 (A tile + B tile)

// ---------------- launch 1: prep reductions + fp16 conversions ----------------
#define CONV_WQ  (Dm*Dm/4)            // 147456 float4
#define CONV_WK  (Dm*Dm/4)
#define CONV_FE  (NFS*Dm/4)           // 196608
#define CONV_TOT (CONV_WQ+CONV_WK+CONV_FE)   // 491520
#define CONV_BLK 480                  // 480*256*4 = 491520

__global__ void __launch_bounds__(256) k1_prep_conv(const float* __restrict__ Wq,
                                                    const float* __restrict__ Wk,
                                                    const float* __restrict__ fe,
                                                    const float* __restrict__ bq,
                                                    const float* __restrict__ Wv,
                                                    const float* __restrict__ wd,
                                                    const float* __restrict__ bv){
  if (blockIdx.x < 193){
    int warp = blockIdx.x*8 + (threadIdx.x >> 5);
    int lane = threadIdx.x & 31;
    if (warp < Dm){
      const float* row = Wv + (size_t)warp*Dm;
      float s=0.f;
      for (int k=lane;k<Dm;k+=32) s += row[k]*wd[k];
      s = warp_sum(s);
      if (!lane) g_wv1[warp]=s;
    } else if (warp < 2*Dm){
      int n = warp - Dm;
      const float* row = Wk + (size_t)n*Dm;
      float s=0.f;
      for (int k=lane;k<Dm;k+=32) s += row[k]*bq[k];
      s = warp_sum(s);
      if (!lane) g_tbias[n]=s;
    } else if (warp == 2*Dm){
      float s=0.f;
      for (int k=lane;k<Dm;k+=32) s += bv[k]*wd[k];
      s = warp_sum(s);
      if (!lane) g_cbv=s;
    }
  } else {
    int base = (blockIdx.x - 193)*256 + threadIdx.x;
    #pragma unroll
    for (int k=0;k<4;k++){
      int i = base + k*(CONV_BLK*256);
      const float4* src; __half2* dst; int off;
      if (i < CONV_WQ){ src = (const float4*)Wq; dst = (__half2*)g_wq16; off = i; }
      else if (i < CONV_WQ+CONV_WK){ src = (const float4*)Wk; dst = (__half2*)g_wk16; off = i-CONV_WQ; }
      else { src = (const float4*)fe; dst = (__half2*)g_fe16; off = i-CONV_WQ-CONV_WK; }
      float4 v = src[off];
      dst[2*off]   = __floats2half2_rn(v.x, v.y);
      dst[2*off+1] = __floats2half2_rn(v.z, v.w);
    }
  }
}

// ---------------- generic HMMA GEMM: C[m,n] = sum_k A[m,k]*B[n,k] (+bias[n]), fp16 out ----------------
// K fixed = 768 (12 chunks of 64). Swizzled smem, 3-stage, 1 sync/chunk.
#define GK 768
#define GKC 12
template<bool BIAS>
__global__ void __launch_bounds__(256,2)
gemm_hmma(const __half* __restrict__ A, const __half* __restrict__ B,
          __half* __restrict__ C, const float* __restrict__ bias, int Ndim){
  extern __shared__ char smem[];
  const uint32_t sb = smem_u32(smem);
  const int tid = threadIdx.x;
  const int lane = tid & 31, wid = tid >> 5;
  const int m0 = blockIdx.x*128, n0 = blockIdx.y*128;
  const int warpM = (wid >> 1)*32;
  const int warpN = (wid & 1)*64;

  const __half* a_f = A + (size_t)m0*GK;
  const __half* b_f = B + (size_t)n0*GK;

  const int cpRow  = tid >> 3;
  const int cpColE = (tid & 7)*8;
  const uint32_t cpColB = (uint32_t)((tid & 7)*16);

  const int rowA = warpM + (lane & 15);
  const uint32_t rA = (uint32_t)(rowA*128), xA = (uint32_t)((rowA & 7) << 4);
  const uint32_t cA0 = (uint32_t)(16*(lane >> 4));
  const int rowB = warpN + 8*((lane >> 4) & 1) + (lane & 7);
  const uint32_t rB = (uint32_t)(rowB*128), xB = (uint32_t)((rowB & 7) << 4);
  const uint32_t cB0 = (uint32_t)(16*((lane >> 3) & 1));

  float acc[2][8][4];
  #pragma unroll
  for (int mt=0;mt<2;mt++)
    #pragma unroll
    for (int nt=0;nt<8;nt++)
      #pragma unroll
      for (int q=0;q<4;q++) acc[mt][nt][q]=0.f;

  auto load_chunk = [&](int slot, int k0){
    uint32_t st = sb + slot*STAGE_B;
    #pragma unroll
    for (int i=0;i<4;i++){
      int row = cpRow + i*32;
      uint32_t so = (uint32_t)(row*128) + (cpColB ^ (uint32_t)((row & 7) << 4));
      cp16(st + so,          a_f + (size_t)row*GK + k0 + cpColE);
      cp16(st + TILE_B + so, b_f + (size_t)row*GK + k0 + cpColE);
    }
    cp_commit();
  };

  load_chunk(0, 0);
  load_chunk(1, 64);
  int ldslot = 2, curslot = 0;
  #pragma unroll 1
  for (int kc=0; kc<GKC; kc++){
    if (kc < GKC-1) cp_wait<1>(); else cp_wait<0>();
    __syncthreads();
    if (kc < GKC-2){
      load_chunk(ldslot, (kc+2)*64);
      if (++ldslot == 3) ldslot = 0;
    }
    uint32_t st = sb + curslot*STAGE_B;
    if (++curslot == 3) curslot = 0;
    uint32_t tA = st, tB = st + TILE_B;
    #pragma unroll
    for (int kk=0; kk<4; kk++){
      uint32_t cA = (cA0 + kk*32) ^ xA;
      uint32_t cB = (cB0 + kk*32) ^ xB;
      uint32_t ah[2][4];
      #pragma unroll
      for (int mt=0; mt<2; mt++)
        LDSM4(ah[mt][0],ah[mt][1],ah[mt][2],ah[mt][3], tA + rA + mt*2048 + cA);
      #pragma unroll
      for (int p=0; p<4; p++){
        uint32_t b0,b1,b2,b3;
        LDSM4(b0,b1,b2,b3, tB + rB + p*2048 + cB);
        #pragma unroll
        for (int mt=0; mt<2; mt++){
          mma16816(acc[mt][2*p],   ah[mt][0],ah[mt][1],ah[mt][2],ah[mt][3], b0, b1);
          mma16816(acc[mt][2*p+1], ah[mt][0],ah[mt][1],ah[mt][2],ah[mt][3], b2, b3);
        }
      }
    }
  }

  // epilogue: fp16 store (+bias)
  const int lq = lane & 3, lr = lane >> 2;
  #pragma unroll
  for (int mt=0; mt<2; mt++)
    #pragma unroll
    for (int nt=0; nt<8; nt++){
      int col = n0 + warpN + nt*8 + 2*lq;
      float b0 = 0.f, b1 = 0.f;
      if (BIAS){ b0 = bias[col]; b1 = bias[col+1]; }
      #pragma unroll
      for (int g=0; g<2; g++){
        int row = m0 + warpM + mt*16 + g*8 + lr;
        __half2 h = __floats2half2_rn(acc[mt][nt][g*2] + b0, acc[mt][nt][g*2+1] + b1);
        *(__half2*)(C + (size_t)row*Ndim + col) = h;
      }
    }
}

// ---------------- v1 + law_embs -> fp16 (one streaming pass) ----------------
__global__ void v1y_kernel(const float* __restrict__ y){
  int row = (blockIdx.x*blockDim.x + threadIdx.x) >> 5;
  if (row >= LC*SEQm) return;
  int lane = threadIdx.x & 31;
  const float4* p = (const float4*)(y + (size_t)row*Dm);
  __half2* oh = (__half2*)(g_y_f16 + (size_t)row*Dm);
  float s = 0.f;
  #pragma unroll
  for (int k=lane;k<Dm/4;k+=32){
    float4 a = p[k];
    float4 w = *(const float4*)(g_wv1 + 4*k);
    s += a.x*w.x + a.y*w.y + a.z*w.z + a.w*w.w;
    oh[2*k]   = __floats2half2_rn(a.x, a.y);
    oh[2*k+1] = __floats2half2_rn(a.z, a.w);
  }
  s = warp_sum(s);
  if (!lane) g_v1[row] = s + g_cbv;
}

// ---------------- fused mma.sync attention (swizzled, 3-stage, 1 sync/chunk, occ=2) ----------------
#define SM_V1   (3*STAGE_B)           // 98304
#define SM_MS   (SM_V1 + 512)
#define SM_PM   (SM_MS + 512)         // float[2][128]
#define SM_PS   (SM_PM + 1024)
#define SM_PA   (SM_PS + 1024)
#define ATTN_SMEM (SM_PA + 1024)      // 102400

__global__ void __launch_bounds__(256,2)
attn_mma_kernel(const float* __restrict__ mask, const float* __restrict__ bdp){
  extern __shared__ char smem[];
  const uint32_t sb = smem_u32(smem);
  const int tid = threadIdx.x;
  const int lane = tid & 31, wid = tid >> 5;
  const int l = blockIdx.y, m0 = blockIdx.x*128;
  const int warpM = (wid >> 1)*32;
  const int warpN = (wid & 1)*64;

  float* v1s = (float*)(smem + SM_V1);
  float* ms  = (float*)(smem + SM_MS);
  float* pm  = (float*)(smem + SM_PM);
  float* ps  = (float*)(smem + SM_PS);
  float* pa  = (float*)(smem + SM_PA);

  const __half* yl_f = g_y_f16 + (size_t)l*SEQm*Dm;
  const __half* a_f  = g_t_f16 + (size_t)m0*Dm;

  const int cpRow  = tid >> 3;
  const int cpColE = (tid & 7)*8;
  const uint32_t cpColB = (uint32_t)((tid & 7)*16);

  const int rowA = warpM + (lane & 15);
  const uint32_t rA = (uint32_t)(rowA*128), xA = (uint32_t)((rowA & 7) << 4);
  const uint32_t cA0 = (uint32_t)(16*(lane >> 4));
  const int rowB = warpN + 8*((lane >> 4) & 1) + (lane & 7);
  const uint32_t rB = (uint32_t)(rowB*128), xB = (uint32_t)((rowB & 7) << 4);
  const uint32_t cB0 = (uint32_t)(16*((lane >> 3) & 1));

  const float scl = 0.03608439182435161f;   // 1/sqrt(768)
  float row_m = -1e30f, row_s = 0.f, row_a = 0.f;

  for (int nc=0; nc<4; nc++){
    const int n0 = nc*128;
    __syncthreads();
    if (tid < 128){
      v1s[tid] = g_v1[l*SEQm + n0 + tid];
      ms[tid]  = mask[l*SEQm + n0 + tid];
    }

    float acc[2][8][4];
    #pragma unroll
    for (int mt=0;mt<2;mt++)
      #pragma unroll
      for (int nt=0;nt<8;nt++)
        #pragma unroll
        for (int q=0;q<4;q++) acc[mt][nt][q]=0.f;

    auto load_chunk = [&](int slot, int k0){
      uint32_t st = sb + slot*STAGE_B;
      #pragma unroll
      for (int i=0;i<4;i++){
        int row = cpRow + i*32;
        uint32_t so = (uint32_t)(row*128) + (cpColB ^ (uint32_t)((row & 7) << 4));
        cp16(st + so,          a_f  + (size_t)row*Dm + k0 + cpColE);
        cp16(st + TILE_B + so, yl_f + (size_t)(n0+row)*Dm + k0 + cpColE);
      }
      cp_commit();
    };

    load_chunk(0, 0);
    load_chunk(1, 64);
    int ldslot = 2, curslot = 0;
    #pragma unroll 1
    for (int kc=0; kc<12; kc++){
      if (kc < 11) cp_wait<1>(); else cp_wait<0>();
      __syncthreads();
      if (kc < 10){
        load_chunk(ldslot, (kc+2)*64);
        if (++ldslot == 3) ldslot = 0;
      }
      uint32_t st = sb + curslot*STAGE_B;
      if (++curslot == 3) curslot = 0;
      uint32_t tA = st, tB = st + TILE_B;
      #pragma unroll
      for (int kk=0; kk<4; kk++){
        uint32_t cA = (cA0 + kk*32) ^ xA;
        uint32_t cB = (cB0 + kk*32) ^ xB;
        uint32_t ah[2][4];
        #pragma unroll
        for (int mt=0; mt<2; mt++)
          LDSM4(ah[mt][0],ah[mt][1],ah[mt][2],ah[mt][3], tA + rA + mt*2048 + cA);
        #pragma unroll
        for (int p=0; p<4; p++){
          uint32_t b0,b1,b2,b3;
          LDSM4(b0,b1,b2,b3, tB + rB + p*2048 + cB);
          #pragma unroll
          for (int mt=0; mt<2; mt++){
            mma16816(acc[mt][2*p],   ah[mt][0],ah[mt][1],ah[mt][2],ah[mt][3], b0, b1);
            mma16816(acc[mt][2*p+1], ah[mt][0],ah[mt][1],ah[mt][2],ah[mt][3], b2, b3);
          }
        }
      }
    }

    // ---- register softmax epilogue ----
    {
      const int lq = lane & 3;
      const int lr = lane >> 2;
      #pragma unroll
      for (int mt=0; mt<2; mt++)
        #pragma unroll
        for (int g=0; g<2; g++){
          float sc[16];
          float mx = -1e30f;
          #pragma unroll
          for (int nt=0; nt<8; nt++)
            #pragma unroll
            for (int p=0; p<2; p++){
              int c = warpN + nt*8 + 2*lq + p;
              float v = acc[mt][nt][g*2+p]*scl + ms[c];
              sc[nt*2+p] = v;
              mx = fmaxf(mx, v);
            }
          mx = fmaxf(mx, __shfl_xor_sync(0xffffffffu, mx, 1));
          mx = fmaxf(mx, __shfl_xor_sync(0xffffffffu, mx, 2));
          float ss = 0.f, aa = 0.f;
          #pragma unroll
          for (int nt=0; nt<8; nt++)
            #pragma unroll
            for (int p=0; p<2; p++){
              int c = warpN + nt*8 + 2*lq + p;
              float e = __expf(sc[nt*2+p] - mx);
              ss += e; aa += e*v1s[c];
            }
          ss += __shfl_xor_sync(0xffffffffu, ss, 1);
          ss += __shfl_xor_sync(0xffffffffu, ss, 2);
          aa += __shfl_xor_sync(0xffffffffu, aa, 1);
          aa += __shfl_xor_sync(0xffffffffu, aa, 2);
          if (lq == 0){
            int row = warpM + mt*16 + g*8 + lr;
            int h = wid & 1;
            pm[h*128+row]=mx; ps[h*128+row]=ss; pa[h*128+row]=aa;
          }
        }
    }
    __syncthreads();
    if (tid < 128){
      int r = tid;
      float m0h=pm[r], m1h=pm[128+r];
      float m01 = fmaxf(m0h, m1h);
      float s01 = ps[r]*__expf(m0h-m01) + ps[128+r]*__expf(m1h-m01);
      float a01 = pa[r]*__expf(m0h-m01) + pa[128+r]*__expf(m1h-m01);
      float nm = fmaxf(row_m, m01);
      float c1 = __expf(row_m-nm), c2 = __expf(m01-nm);
      row_s = row_s*c1 + s01*c2;
      row_a = row_a*c1 + a01*c2;
      row_m = nm;
    }
  }

  if (tid < 128){
    int fs = m0 + tid;
    int f = fs >> 9, si = fs & 511;
    g_laws2[((size_t)f*LC + l)*SEQm + si] = row_a/row_s + bdp[0];
  }
}

// ---------------- head (includes scores2) ----------------
__global__ void head_kernel(const float* __restrict__ output,
                            const float* __restrict__ laws_table,
                            const float* __restrict__ wlp,    const float* __restrict__ blp,
                            const float* __restrict__ W_law,  const float* __restrict__ b_law,
                            const float* __restrict__ W_rule, const float* __restrict__ b_rule,
                            const float* __restrict__ W_fact, const float* __restrict__ b_fact,
                            const float* __restrict__ W_accu, const float* __restrict__ b_accu,
                            const float* __restrict__ W_term, const float* __restrict__ b_term,
                            float* __restrict__ out){
  __shared__ float cls_s[2][Dm];
  __shared__ float law0_s[2][LC];
  __shared__ float law_s[2][LC];
  __shared__ float sc2_s[2*LC];
  __shared__ int   lawno_s[2];
  int tid = threadIdx.x;
  int wid = tid >> 5, lane = tid & 31;

  for (int row = wid; row < 2*LC; row += 8){
    const float* p = g_laws2 + (size_t)row*SEQm;
    float s=0.f;
    for (int k=lane;k<SEQm;k+=32) s += p[k]*wlp[k];
    s = warp_sum(s);
    if (!lane) sc2_s[row] = s + blp[0];
  }
  for (int i=tid;i<2*Dm;i+=256)
    cls_s[i/Dm][i%Dm] = output[(size_t)(i/Dm)*SEQm*Dm + (i%Dm)];
  __syncthreads();
  for (int job=tid;job<206+2*ACLS+2*TCLS;job+=256){
    if (job<206){
      int f=job/LC, c=job%LC;
      float s=0.f;
      for (int d=0;d<Dm;d++) s += cls_s[f][d]*W_law[(size_t)d*LC+c];
      law0_s[f][c] = s + b_law[c];
    } else if (job<206+2*ACLS){
      int q=job-206; int f=q/ACLS, c=q%ACLS;
      float s=0.f;
      for (int d=0;d<Dm;d++) s += cls_s[f][d]*W_accu[(size_t)d*ACLS+c];
      out[206+q] = s + b_accu[c];
    } else {
      int q=job-(206+2*ACLS); int f=q/TCLS, c=q%TCLS;
      float s=0.f;
      for (int d=0;d<Dm;d++) s += cls_s[f][d]*W_term[(size_t)d*TCLS+c];
      out[206+2*ACLS+q] = s + b_term[c];
    }
  }
  __syncthreads();
  for (int job=tid;job<2*LC;job+=256){
    int f=job/LC, c=job%LC;
    float s = b_rule[c] + b_fact[c];
    for (int j=0;j<LC;j++)
      s += law0_s[f][j]*W_rule[(size_t)j*LC+c] + sc2_s[f*LC+j]*W_fact[(size_t)j*LC+c];
    law_s[f][c]=s;
    out[job]=s;
  }
  __syncthreads();
  if (tid<2){
    int best=0; float bvv=law_s[tid][0];
    for (int c=1;c<LC;c++) if (law_s[tid][c]>bvv){ bvv=law_s[tid][c]; best=c; }
    lawno_s[tid]=best;
    out[2*LC+2*ACLS+2*TCLS+2*LC+tid] = (float)best;
  }
  __syncthreads();
  for (int job=tid;job<2*LC;job+=256){
    int f=job/LC, c=job%LC;
    const float* lb = laws_table + (size_t)lawno_s[f]*Dm;
    float s=0.f;
    for (int d=0;d<Dm;d++) s += lb[d]*W_law[(size_t)d*LC+c];
    out[2*LC+2*ACLS+2*TCLS+job] = s + b_law[c];
  }
}

// ---------------- launch ----------------
extern "C" void kernel_launch(void* const* d_in, const int* in_sizes, int n_in,
                              void* d_out, int out_size){
  const float* output     = (const float*)d_in[0];
  const float* fact_emb   = (const float*)d_in[1];
  const float* law_embs   = (const float*)d_in[2];
  const float* law_masks  = (const float*)d_in[3];
  const float* laws_table = (const float*)d_in[4];
  const float* Wq  = (const float*)d_in[5];
  const float* bq  = (const float*)d_in[6];
  const float* Wk  = (const float*)d_in[7];
  // d_in[8] = bk : softmax-invariant, drops out
  const float* Wv  = (const float*)d_in[9];
  const float* bv  = (const float*)d_in[10];
  const float* w_dprob   = (const float*)d_in[11];
  const float* b_dprob   = (const float*)d_in[12];
  const float* w_lawprob = (const float*)d_in[13];
  const float* b_lawprob = (const float*)d_in[14];
  const float* W_rulelaw = (const float*)d_in[15];
  const float* b_rulelaw = (const float*)d_in[16];
  const float* W_factlaw = (const float*)d_in[17];
  const float* b_factlaw = (const float*)d_in[18];
  const float* W_law = (const float*)d_in[19];
  const float* b_law = (const float*)d_in[20];
  const float* W_accu = (const float*)d_in[21];
  const float* b_accu = (const float*)d_in[22];
  const float* W_term = (const float*)d_in[23];
  const float* b_term = (const float*)d_in[24];
  float* out = (float*)d_out;

  void *pWq16=nullptr, *pWk16=nullptr, *pFe16=nullptr, *pMt16=nullptr, *pT16=nullptr, *pTb=nullptr;
  cudaGetSymbolAddress(&pWq16, g_wq16);
  cudaGetSymbolAddress(&pWk16, g_wk16);
  cudaGetSymbolAddress(&pFe16, g_fe16);
  cudaGetSymbolAddress(&pMt16, g_mt16);
  cudaGetSymbolAddress(&pT16,  g_t_f16);
  cudaGetSymbolAddress(&pTb,   g_tbias);

  cudaFuncSetAttribute(attn_mma_kernel, cudaFuncAttributeMaxDynamicSharedMemorySize, ATTN_SMEM);
  cudaFuncSetAttribute(gemm_hmma<false>, cudaFuncAttributeMaxDynamicSharedMemorySize, 3*STAGE_B);
  cudaFuncSetAttribute(gemm_hmma<true>,  cudaFuncAttributeMaxDynamicSharedMemorySize, 3*STAGE_B);

  k1_prep_conv<<<193 + CONV_BLK, 256>>>(Wq, Wk, fact_emb, bq, Wv, w_dprob, bv);
  // MT[j,i] = sum_k Wk[j,k]*Wq[i,k]
  gemm_hmma<false><<<dim3(Dm/128, Dm/128), 256, 3*STAGE_B>>>(
      (const __half*)pWk16, (const __half*)pWq16, (__half*)pMt16, nullptr, Dm);
  // t[fs,j] = sum_i fe[fs,i]*MT[j,i] + tbias[j]
  gemm_hmma<true><<<dim3(NFS/128, Dm/128), 256, 3*STAGE_B>>>(
      (const __half*)pFe16, (const __half*)pMt16, (__half*)pT16, (const float*)pTb, Dm);
  v1y_kernel<<<(LC*SEQm + 7)/8, 256>>>(law_embs);
  attn_mma_kernel<<<dim3(NFS/128, LC), 256, ATTN_SMEM>>>(law_masks, b_dprob);
  head_kernel<<<1,256>>>(output, laws_table, w_lawprob, b_lawprob,
                         W_law, b_law, W_rulelaw, b_rulelaw,
                         W_factlaw, b_factlaw, W_accu, b_accu, W_term, b_term, out);
}

// round 8
// speedup vs baseline: 6.1280x; 1.2643x over previous
#include <cuda_runtime.h>
#include <cuda_bf16.h>
#include <cuda_fp16.h>
#include <math.h>
#include <cstdint>

#define Dm   768
#define SEQm 512
#define NFS  1024   // B(2) * S(512)
#define LC   103
#define ACLS 119
#define TCLS 11

// ---------------- scratch (static device globals; no allocation) ----------------
__device__ float g_wv1[Dm];         // Wv @ w_dprob
__device__ float g_tbias[Dm];       // Wk @ bq
__device__ float g_cbv;             // bv . w_dprob
__device__ float g_v1[LC*SEQm];     // law_embs . wv1 + cbv
__device__ float g_laws2[2*LC*SEQm];
__device__ float g_law0[2*LC];      // cls @ W_law + b_law
__device__ __half g_wq16[Dm*Dm];
__device__ __half g_wk16[Dm*Dm];
__device__ __half g_fe16[NFS*Dm];
__device__ __half g_mt16[Dm*Dm];    // MT[j,i] = sum_k Wk[j,k] Wq[i,k]
__device__ __half g_t_f16[NFS*Dm];
__device__ __half g_y_f16[(size_t)LC*SEQm*Dm];

__device__ __forceinline__ float warp_sum(float s){
  #pragma unroll
  for (int o=16;o>0;o>>=1) s += __shfl_xor_sync(0xffffffffu, s, o);
  return s;
}

__device__ __forceinline__ uint32_t smem_u32(const void* p){
  uint32_t a;
  asm("{ .reg .u64 t; cvta.to.shared.u64 t, %1; cvt.u32.u64 %0, t; }" : "=r"(a) : "l"(p));
  return a;
}

// ---------------- cp.async helpers ----------------
__device__ __forceinline__ void cp16(uint32_t dst, const void* src){
  asm volatile("cp.async.cg.shared.global [%0], [%1], 16;" :: "r"(dst), "l"(src) : "memory");
}
__device__ __forceinline__ void cp_commit(){ asm volatile("cp.async.commit_group;" ::: "memory"); }
template<int N> __device__ __forceinline__ void cp_wait(){ asm volatile("cp.async.wait_group %0;" :: "n"(N) : "memory"); }

#define LDSM4(r0,r1,r2,r3,addr) \
  asm volatile("ldmatrix.sync.aligned.m8n8.x4.shared.b16 {%0,%1,%2,%3}, [%4];" \
    : "=r"(r0), "=r"(r1), "=r"(r2), "=r"(r3) : "r"(addr))

__device__ __forceinline__ void mma16816(float* c, uint32_t a0, uint32_t a1, uint32_t a2, uint32_t a3,
                                         uint32_t b0, uint32_t b1){
  asm volatile("mma.sync.aligned.m16n8k16.row.col.f32.f16.f16.f32 "
    "{%0,%1,%2,%3}, {%4,%5,%6,%7}, {%8,%9}, {%0,%1,%2,%3};"
    : "+f"(c[0]), "+f"(c[1]), "+f"(c[2]), "+f"(c[3])
    : "r"(a0), "r"(a1), "r"(a2), "r"(a3), "r"(b0), "r"(b1));
}

// shared tile geometry
#define TILE_B  16384                 // 128 rows x 128B (64 fp16), SW128-xor swizzled
#define STAGE_B (2*TILE_B)            // 32768 (A tile + B tile)
#define GEMM_SMEM (3*STAGE_B)         // 98304

// ---------------- generic HMMA GEMM body: C[m,n] = sum_k A[m,k]*B[n,k] (+bias), fp16 out ----------------
#define GK 768
#define GKC 12
__device__ __forceinline__ void gemm_body(const __half* __restrict__ A, const __half* __restrict__ B,
                                          __half* __restrict__ C, const float* __restrict__ bias,
                                          int Ndim, int m0, int n0, char* smem){
  const uint32_t sb = smem_u32(smem);
  const int tid = threadIdx.x;
  const int lane = tid & 31, wid = tid >> 5;
  const int warpM = (wid >> 1)*32;
  const int warpN = (wid & 1)*64;

  const __half* a_f = A + (size_t)m0*GK;
  const __half* b_f = B + (size_t)n0*GK;

  const int cpRow  = tid >> 3;
  const int cpColE = (tid & 7)*8;
  const uint32_t cpColB = (uint32_t)((tid & 7)*16);

  const int rowA = warpM + (lane & 15);
  const uint32_t rA = (uint32_t)(rowA*128), xA = (uint32_t)((rowA & 7) << 4);
  const uint32_t cA0 = (uint32_t)(16*(lane >> 4));
  const int rowB = warpN + 8*((lane >> 4) & 1) + (lane & 7);
  const uint32_t rB = (uint32_t)(rowB*128), xB = (uint32_t)((rowB & 7) << 4);
  const uint32_t cB0 = (uint32_t)(16*((lane >> 3) & 1));

  float acc[2][8][4];
  #pragma unroll
  for (int mt=0;mt<2;mt++)
    #pragma unroll
    for (int nt=0;nt<8;nt++)
      #pragma unroll
      for (int q=0;q<4;q++) acc[mt][nt][q]=0.f;

  auto load_chunk = [&](int slot, int k0){
    uint32_t st = sb + slot*STAGE_B;
    #pragma unroll
    for (int i=0;i<4;i++){
      int row = cpRow + i*32;
      uint32_t so = (uint32_t)(row*128) + (cpColB ^ (uint32_t)((row & 7) << 4));
      cp16(st + so,          a_f + (size_t)row*GK + k0 + cpColE);
      cp16(st + TILE_B + so, b_f + (size_t)row*GK + k0 + cpColE);
    }
    cp_commit();
  };

  load_chunk(0, 0);
  load_chunk(1, 64);
  int ldslot = 2, curslot = 0;
  #pragma unroll 1
  for (int kc=0; kc<GKC; kc++){
    if (kc < GKC-1) cp_wait<1>(); else cp_wait<0>();
    __syncthreads();
    if (kc < GKC-2){
      load_chunk(ldslot, (kc+2)*64);
      if (++ldslot == 3) ldslot = 0;
    }
    uint32_t st = sb + curslot*STAGE_B;
    if (++curslot == 3) curslot = 0;
    uint32_t tA = st, tB = st + TILE_B;
    #pragma unroll
    for (int kk=0; kk<4; kk++){
      uint32_t cA = (cA0 + kk*32) ^ xA;
      uint32_t cB = (cB0 + kk*32) ^ xB;
      uint32_t ah[2][4];
      #pragma unroll
      for (int mt=0; mt<2; mt++)
        LDSM4(ah[mt][0],ah[mt][1],ah[mt][2],ah[mt][3], tA + rA + mt*2048 + cA);
      #pragma unroll
      for (int p=0; p<4; p++){
        uint32_t b0,b1,b2,b3;
        LDSM4(b0,b1,b2,b3, tB + rB + p*2048 + cB);
        #pragma unroll
        for (int mt=0; mt<2; mt++){
          mma16816(acc[mt][2*p],   ah[mt][0],ah[mt][1],ah[mt][2],ah[mt][3], b0, b1);
          mma16816(acc[mt][2*p+1], ah[mt][0],ah[mt][1],ah[mt][2],ah[mt][3], b2, b3);
        }
      }
    }
  }

  const int lq = lane & 3, lr = lane >> 2;
  #pragma unroll
  for (int mt=0; mt<2; mt++)
    #pragma unroll
    for (int nt=0; nt<8; nt++){
      int col = n0 + warpN + nt*8 + 2*lq;
      float b0 = 0.f, b1 = 0.f;
      if (bias){ b0 = bias[col]; b1 = bias[col+1]; }
      #pragma unroll
      for (int g=0; g<2; g++){
        int row = m0 + warpM + mt*16 + g*8 + lr;
        __half2 h = __floats2half2_rn(acc[mt][nt][g*2] + b0, acc[mt][nt][g*2+1] + b1);
        *(__half2*)(C + (size_t)row*Ndim + col) = h;
      }
    }
}

// ---------------- launch 1: prep reductions + fp16 conversions + head-dots ----------------
#define CONV_WQ  (Dm*Dm/4)            // 147456 float4
#define CONV_WK  (Dm*Dm/4)
#define CONV_FE  (NFS*Dm/4)           // 196608
#define CONV_BLK 480                  // 480*256*4 = 491520
#define DOTS_BLK 59                   // 59*8 = 472 >= 466 warp-dots

__global__ void __launch_bounds__(256) k1_prep(const float* __restrict__ Wq,
                                               const float* __restrict__ Wk,
                                               const float* __restrict__ fe,
                                               const float* __restrict__ bq,
                                               const float* __restrict__ Wv,
                                               const float* __restrict__ wd,
                                               const float* __restrict__ bv,
                                               const float* __restrict__ output,
                                               const float* __restrict__ W_law,  const float* __restrict__ b_law,
                                               const float* __restrict__ W_accu, const float* __restrict__ b_accu,
                                               const float* __restrict__ W_term, const float* __restrict__ b_term,
                                               float* __restrict__ out){
  int lane = threadIdx.x & 31;
  if (blockIdx.x < 193){
    int warp = blockIdx.x*8 + (threadIdx.x >> 5);
    if (warp < Dm){
      const float* row = Wv + (size_t)warp*Dm;
      float s=0.f;
      for (int k=lane;k<Dm;k+=32) s += row[k]*wd[k];
      s = warp_sum(s);
      if (!lane) g_wv1[warp]=s;
    } else if (warp < 2*Dm){
      int n = warp - Dm;
      const float* row = Wk + (size_t)n*Dm;
      float s=0.f;
      for (int k=lane;k<Dm;k+=32) s += row[k]*bq[k];
      s = warp_sum(s);
      if (!lane) g_tbias[n]=s;
    } else if (warp == 2*Dm){
      float s=0.f;
      for (int k=lane;k<Dm;k+=32) s += bv[k]*wd[k];
      s = warp_sum(s);
      if (!lane) g_cbv=s;
    }
  } else if (blockIdx.x < 193 + CONV_BLK){
    int base = (blockIdx.x - 193)*256 + threadIdx.x;
    #pragma unroll
    for (int k=0;k<4;k++){
      int i = base + k*(CONV_BLK*256);
      const float4* src; __half2* dst; int off;
      if (i < CONV_WQ){ src = (const float4*)Wq; dst = (__half2*)g_wq16; off = i; }
      else if (i < CONV_WQ+CONV_WK){ src = (const float4*)Wk; dst = (__half2*)g_wk16; off = i-CONV_WQ; }
      else { src = (const float4*)fe; dst = (__half2*)g_fe16; off = i-CONV_WQ-CONV_WK; }
      float4 v = src[off];
      dst[2*off]   = __floats2half2_rn(v.x, v.y);
      dst[2*off+1] = __floats2half2_rn(v.z, v.w);
    }
  } else {
    // head-dots: law0 (206), accu (238), term (22)
    int w = (blockIdx.x - 193 - CONV_BLK)*8 + (threadIdx.x >> 5);
    if (w < 206){
      int f=w/LC, c=w%LC;
      const float* cls = output + (size_t)f*SEQm*Dm;
      float s=0.f;
      for (int d=lane; d<Dm; d+=32) s += cls[d]*W_law[(size_t)d*LC+c];
      s = warp_sum(s);
      if (!lane) g_law0[w] = s + b_law[c];
    } else if (w < 444){
      int q=w-206; int f=q/ACLS, c=q%ACLS;
      const float* cls = output + (size_t)f*SEQm*Dm;
      float s=0.f;
      for (int d=lane; d<Dm; d+=32) s += cls[d]*W_accu[(size_t)d*ACLS+c];
      s = warp_sum(s);
      if (!lane) out[206+q] = s + b_accu[c];
    } else if (w < 466){
      int q=w-444; int f=q/TCLS, c=q%TCLS;
      const float* cls = output + (size_t)f*SEQm*Dm;
      float s=0.f;
      for (int d=lane; d<Dm; d+=32) s += cls[d]*W_term[(size_t)d*TCLS+c];
      s = warp_sum(s);
      if (!lane) out[444+q] = s + b_term[c];
    }
  }
}

// ---------------- launch 2: combo = gemmMT (36 blocks) + v1y (6592 blocks) ----------------
__global__ void __launch_bounds__(256,2) k2_mt_v1y(const float* __restrict__ y){
  extern __shared__ char smem[];
  if (blockIdx.x < 36){
    gemm_body(g_wk16, g_wq16, g_mt16, nullptr, Dm,
              (blockIdx.x % 6)*128, (blockIdx.x / 6)*128, smem);
  } else {
    int row = (blockIdx.x - 36)*8 + (threadIdx.x >> 5);
    if (row >= LC*SEQm) return;
    int lane = threadIdx.x & 31;
    const float4* p = (const float4*)(y + (size_t)row*Dm);
    __half2* oh = (__half2*)(g_y_f16 + (size_t)row*Dm);
    float s = 0.f;
    #pragma unroll
    for (int k=lane;k<Dm/4;k+=32){
      float4 a = p[k];
      float4 w = *(const float4*)(g_wv1 + 4*k);
      s += a.x*w.x + a.y*w.y + a.z*w.z + a.w*w.w;
      oh[2*k]   = __floats2half2_rn(a.x, a.y);
      oh[2*k+1] = __floats2half2_rn(a.z, a.w);
    }
    s = warp_sum(s);
    if (!lane) g_v1[row] = s + g_cbv;
  }
}

// ---------------- launch 3: t = fe @ MT^T + tbias (fp16 out) ----------------
__global__ void __launch_bounds__(256,2) gemmT(){
  extern __shared__ char smem[];
  gemm_body(g_fe16, g_mt16, g_t_f16, g_tbias, Dm,
            blockIdx.x*128, blockIdx.y*128, smem);
}

// ---------------- launch 4: fused attention (flattened 48-chunk pipeline) ----------------
#define SM_V1   (3*STAGE_B)           // 98304, float[2][128]
#define SM_MS   (SM_V1 + 1024)        // float[2][128]
#define SM_PM   (SM_MS + 1024)        // float[2][128]
#define SM_PS   (SM_PM + 1024)
#define SM_PA   (SM_PS + 1024)
#define ATTN_SMEM (SM_PA + 1024)      // 103424

__global__ void __launch_bounds__(256,2)
attn_mma_kernel(const float* __restrict__ mask, const float* __restrict__ bdp){
  extern __shared__ char smem[];
  const uint32_t sb = smem_u32(smem);
  const int tid = threadIdx.x;
  const int lane = tid & 31, wid = tid >> 5;
  const int l = blockIdx.y, m0 = blockIdx.x*128;
  const int warpM = (wid >> 1)*32;
  const int warpN = (wid & 1)*64;

  float* v1s = (float*)(smem + SM_V1);
  float* ms  = (float*)(smem + SM_MS);
  float* pm  = (float*)(smem + SM_PM);
  float* ps  = (float*)(smem + SM_PS);
  float* pa  = (float*)(smem + SM_PA);

  const __half* yl_f = g_y_f16 + (size_t)l*SEQm*Dm;
  const __half* a_f  = g_t_f16 + (size_t)m0*Dm;

  const int cpRow  = tid >> 3;
  const int cpColE = (tid & 7)*8;
  const uint32_t cpColB = (uint32_t)((tid & 7)*16);

  const int rowA = warpM + (lane & 15);
  const uint32_t rA = (uint32_t)(rowA*128), xA = (uint32_t)((rowA & 7) << 4);
  const uint32_t cA0 = (uint32_t)(16*(lane >> 4));
  const int rowB = warpN + 8*((lane >> 4) & 1) + (lane & 7);
  const uint32_t rB = (uint32_t)(rowB*128), xB = (uint32_t)((rowB & 7) << 4);
  const uint32_t cB0 = (uint32_t)(16*((lane >> 3) & 1));

  const float scl = 0.03608439182435161f;   // 1/sqrt(768)
  float row_m = -1e30f, row_s = 0.f, row_a = 0.f;

  float acc[2][8][4];
  #pragma unroll
  for (int mt=0;mt<2;mt++)
    #pragma unroll
    for (int nt=0;nt<8;nt++)
      #pragma unroll
      for (int q=0;q<4;q++) acc[mt][nt][q]=0.f;

  // chunk g (0..47): n0 = (g/12)*128, k0 = (g%12)*64; slot = g%3
  auto load_chunk = [&](int slot, int g){
    const int n0 = (g/12)*128, k0 = (g%12)*64;
    uint32_t st = sb + slot*STAGE_B;
    #pragma unroll
    for (int i=0;i<4;i++){
      int row = cpRow + i*32;
      uint32_t so = (uint32_t)(row*128) + (cpColB ^ (uint32_t)((row & 7) << 4));
      cp16(st + so,          a_f  + (size_t)row*Dm + k0 + cpColE);
      cp16(st + TILE_B + so, yl_f + (size_t)(n0+row)*Dm + k0 + cpColE);
    }
    cp_commit();
  };

  load_chunk(0, 0);
  load_chunk(1, 1);
  int ldslot = 2, curslot = 0;
  #pragma unroll 1
  for (int g=0; g<48; g++){
    if (g < 47) cp_wait<1>(); else cp_wait<0>();
    __syncthreads();
    if (g+2 < 48){
      load_chunk(ldslot, g+2);
      if (++ldslot == 3) ldslot = 0;
    }
    if ((g % 12) == 0 && tid < 128){
      const int nc = g/12, n0 = nc*128, buf = (nc & 1)*128;
      v1s[buf + tid] = g_v1[l*SEQm + n0 + tid];
      ms [buf + tid] = mask[l*SEQm + n0 + tid];
    }
    uint32_t st = sb + curslot*STAGE_B;
    if (++curslot == 3) curslot = 0;
    uint32_t tA = st, tB = st + TILE_B;
    #pragma unroll
    for (int kk=0; kk<4; kk++){
      uint32_t cA = (cA0 + kk*32) ^ xA;
      uint32_t cB = (cB0 + kk*32) ^ xB;
      uint32_t ah[2][4];
      #pragma unroll
      for (int mt=0; mt<2; mt++)
        LDSM4(ah[mt][0],ah[mt][1],ah[mt][2],ah[mt][3], tA + rA + mt*2048 + cA);
      #pragma unroll
      for (int p=0; p<4; p++){
        uint32_t b0,b1,b2,b3;
        LDSM4(b0,b1,b2,b3, tB + rB + p*2048 + cB);
        #pragma unroll
        for (int mt=0; mt<2; mt++){
          mma16816(acc[mt][2*p],   ah[mt][0],ah[mt][1],ah[mt][2],ah[mt][3], b0, b1);
          mma16816(acc[mt][2*p+1], ah[mt][0],ah[mt][1],ah[mt][2],ah[mt][3], b2, b3);
        }
      }
    }

    if ((g % 12) == 11){
      const int nc = g/12, buf = (nc & 1)*128;
      // ---- register softmax epilogue ----
      {
        const int lq = lane & 3;
        const int lr = lane >> 2;
        #pragma unroll
        for (int mt=0; mt<2; mt++)
          #pragma unroll
          for (int gg=0; gg<2; gg++){
            float sc[16];
            float mx = -1e30f;
            #pragma unroll
            for (int nt=0; nt<8; nt++)
              #pragma unroll
              for (int p=0; p<2; p++){
                int c = warpN + nt*8 + 2*lq + p;
                float v = acc[mt][nt][gg*2+p]*scl + ms[buf + c];
                sc[nt*2+p] = v;
                mx = fmaxf(mx, v);
              }
            mx = fmaxf(mx, __shfl_xor_sync(0xffffffffu, mx, 1));
            mx = fmaxf(mx, __shfl_xor_sync(0xffffffffu, mx, 2));
            float ss = 0.f, aa = 0.f;
            #pragma unroll
            for (int nt=0; nt<8; nt++)
              #pragma unroll
              for (int p=0; p<2; p++){
                int c = warpN + nt*8 + 2*lq + p;
                float e = __expf(sc[nt*2+p] - mx);
                ss += e; aa += e*v1s[buf + c];
              }
            ss += __shfl_xor_sync(0xffffffffu, ss, 1);
            ss += __shfl_xor_sync(0xffffffffu, ss, 2);
            aa += __shfl_xor_sync(0xffffffffu, aa, 1);
            aa += __shfl_xor_sync(0xffffffffu, aa, 2);
            if (lq == 0){
              int row = warpM + mt*16 + gg*8 + lr;
              int h = wid & 1;
              pm[h*128+row]=mx; ps[h*128+row]=ss; pa[h*128+row]=aa;
            }
          }
      }
      __syncthreads();
      if (tid < 128){
        int r = tid;
        float m0h=pm[r], m1h=pm[128+r];
        float m01 = fmaxf(m0h, m1h);
        float s01 = ps[r]*__expf(m0h-m01) + ps[128+r]*__expf(m1h-m01);
        float a01 = pa[r]*__expf(m0h-m01) + pa[128+r]*__expf(m1h-m01);
        float nm = fmaxf(row_m, m01);
        float c1 = __expf(row_m-nm), c2 = __expf(m01-nm);
        row_s = row_s*c1 + s01*c2;
        row_a = row_a*c1 + a01*c2;
        row_m = nm;
      }
      #pragma unroll
      for (int mt=0;mt<2;mt++)
        #pragma unroll
        for (int nt=0;nt<8;nt++)
          #pragma unroll
          for (int q=0;q<4;q++) acc[mt][nt][q]=0.f;
    }
  }

  if (tid < 128){
    int fs = m0 + tid;
    int f = fs >> 9, si = fs & 511;
    g_laws2[((size_t)f*LC + l)*SEQm + si] = row_a/row_s + bdp[0];
  }
}

// ---------------- launch 5: head (scores2 + law combine + argmax + language gather) ----------------
__global__ void head_kernel(const float* __restrict__ laws_table,
                            const float* __restrict__ wlp,    const float* __restrict__ blp,
                            const float* __restrict__ W_law,  const float* __restrict__ b_law,
                            const float* __restrict__ W_rule, const float* __restrict__ b_rule,
                            const float* __restrict__ W_fact, const float* __restrict__ b_fact,
                            float* __restrict__ out){
  __shared__ float law_s[2][LC];
  __shared__ float sc2_s[2*LC];
  __shared__ int   lawno_s[2];
  int tid = threadIdx.x;
  int wid = tid >> 5, lane = tid & 31;

  for (int row = wid; row < 2*LC; row += 8){
    const float* p = g_laws2 + (size_t)row*SEQm;
    float s=0.f;
    for (int k=lane;k<SEQm;k+=32) s += p[k]*wlp[k];
    s = warp_sum(s);
    if (!lane) sc2_s[row] = s + blp[0];
  }
  __syncthreads();
  for (int job=tid;job<2*LC;job+=256){
    int f=job/LC, c=job%LC;
    float s = b_rule[c] + b_fact[c];
    for (int j=0;j<LC;j++)
      s += g_law0[f*LC+j]*W_rule[(size_t)j*LC+c] + sc2_s[f*LC+j]*W_fact[(size_t)j*LC+c];
    law_s[f][c]=s;
    out[job]=s;
  }
  __syncthreads();
  if (tid<2){
    int best=0; float bvv=law_s[tid][0];
    for (int c=1;c<LC;c++) if (law_s[tid][c]>bvv){ bvv=law_s[tid][c]; best=c; }
    lawno_s[tid]=best;
    out[672+tid] = (float)best;
  }
  __syncthreads();
  for (int job=tid;job<2*LC;job+=256){
    int f=job/LC, c=job%LC;
    const float* lb = laws_table + (size_t)lawno_s[f]*Dm;
    float s=0.f;
    for (int d=0;d<Dm;d++) s += lb[d]*W_law[(size_t)d*LC+c];
    out[466+job] = s + b_law[c];
  }
}

// ---------------- launch ----------------
extern "C" void kernel_launch(void* const* d_in, const int* in_sizes, int n_in,
                              void* d_out, int out_size){
  const float* output     = (const float*)d_in[0];
  const float* fact_emb   = (const float*)d_in[1];
  const float* law_embs   = (const float*)d_in[2];
  const float* law_masks  = (const float*)d_in[3];
  const float* laws_table = (const float*)d_in[4];
  const float* Wq  = (const float*)d_in[5];
  const float* bq  = (const float*)d_in[6];
  const float* Wk  = (const float*)d_in[7];
  // d_in[8] = bk : softmax-invariant, drops out
  const float* Wv  = (const float*)d_in[9];
  const float* bv  = (const float*)d_in[10];
  const float* w_dprob   = (const float*)d_in[11];
  const float* b_dprob   = (const float*)d_in[12];
  const float* w_lawprob = (const float*)d_in[13];
  const float* b_lawprob = (const float*)d_in[14];
  const float* W_rulelaw = (const float*)d_in[15];
  const float* b_rulelaw = (const float*)d_in[16];
  const float* W_factlaw = (const float*)d_in[17];
  const float* b_factlaw = (const float*)d_in[18];
  const float* W_law = (const float*)d_in[19];
  const float* b_law = (const float*)d_in[20];
  const float* W_accu = (const float*)d_in[21];
  const float* b_accu = (const float*)d_in[22];
  const float* W_term = (const float*)d_in[23];
  const float* b_term = (const float*)d_in[24];
  float* out = (float*)d_out;

  cudaFuncSetAttribute(attn_mma_kernel, cudaFuncAttributeMaxDynamicSharedMemorySize, ATTN_SMEM);
  cudaFuncSetAttribute(k2_mt_v1y, cudaFuncAttributeMaxDynamicSharedMemorySize, GEMM_SMEM);
  cudaFuncSetAttribute(gemmT,     cudaFuncAttributeMaxDynamicSharedMemorySize, GEMM_SMEM);

  k1_prep<<<193 + CONV_BLK + DOTS_BLK, 256>>>(Wq, Wk, fact_emb, bq, Wv, w_dprob, bv,
                                              output, W_law, b_law, W_accu, b_accu,
                                              W_term, b_term, out);
  k2_mt_v1y<<<36 + 6592, 256, GEMM_SMEM>>>(law_embs);
  gemmT<<<dim3(NFS/128, Dm/128), 256, GEMM_SMEM>>>();
  attn_mma_kernel<<<dim3(NFS/128, LC), 256, ATTN_SMEM>>>(law_masks, b_dprob);
  head_kernel<<<1,256>>>(laws_table, w_lawprob, b_lawprob,
                         W_law, b_law, W_rulelaw, b_rulelaw,
                         W_factlaw, b_factlaw, out);
}